// round 4
// baseline (speedup 1.0000x reference)
#include <cuda_runtime.h>
#include <math.h>

#define MAXB 2048
#define SEG  8

// scratch (no allocations allowed)
__device__ float g_Mpart[MAXB * SEG * 45];  // per-(batch,seg) Gram upper-tri partials
__device__ float g_cand[MAXB * 21];         // R1(9), R2(9), t(3)
__device__ float g_sc[MAXB * SEG * 4];      // per-(batch,seg) candidate scores

__device__ __forceinline__ void inv3x3(const float* __restrict__ K, float* Ki) {
    float a = K[0], b = K[1], c = K[2];
    float d = K[3], e = K[4], f = K[5];
    float g = K[6], h = K[7], i = K[8];
    float A =  (e * i - f * h);
    float Bc = -(d * i - f * g);
    float C =  (d * h - e * g);
    float det = a * A + b * Bc + c * C;
    float id = 1.0f / det;
    Ki[0] = A * id;             Ki[1] = (c * h - b * i) * id; Ki[2] = (b * f - c * e) * id;
    Ki[3] = Bc * id;            Ki[4] = (a * i - c * g) * id; Ki[5] = (c * d - a * f) * id;
    Ki[6] = C * id;             Ki[7] = (b * g - a * h) * id; Ki[8] = (a * e - b * d) * id;
}

// upper-tri index (i <= j), 9x9 -> 45
#define SU(i, j) ((i) * 9 - (i) * ((i) + 1) / 2 + (j))
// lower-tri index (j <= i)
#define LT(i, j) ((i) * ((i) + 1) / 2 + (j))
// symmetric access of ms[45]
#define ASYM(ms, i, j) ((i) <= (j) ? (ms)[SU(i, j)] : (ms)[SU(j, i)])

// ---------------------------------------------------------------------------
// Kernel A: partial Gram  M_part(b,s) = sum_{n in seg s} w * X X^T
// ---------------------------------------------------------------------------
__global__ __launch_bounds__(256) void k_accumM(
    const float* __restrict__ kpts0, const float* __restrict__ kpts1,
    const float* __restrict__ conf,  const float* __restrict__ K, int N)
{
    int b = blockIdx.x;
    int s = blockIdx.y;
    int NS = (N + SEG - 1) / SEG;
    int n0 = s * NS;
    int n1 = min(N, n0 + NS);

    float Ki0[9], Ki1[9];
    inv3x3(K + (size_t)b * 18, Ki0);
    inv3x3(K + (size_t)b * 18 + 9, Ki1);

    float acc[45];
#pragma unroll
    for (int m = 0; m < 45; ++m) acc[m] = 0.f;

    const float2* p0 = (const float2*)(kpts0 + (size_t)b * N * 2);
    const float2* p1 = (const float2*)(kpts1 + (size_t)b * N * 2);
    const float*  pw = conf + (size_t)b * N;

    for (int n = n0 + threadIdx.x; n < n1; n += blockDim.x) {
        float2 u0 = p0[n];
        float2 u1 = p1[n];
        float  w  = pw[n];
        float x0[3], x1[3], X[9];
        x0[0] = Ki0[0] * u0.x + Ki0[1] * u0.y + Ki0[2];
        x0[1] = Ki0[3] * u0.x + Ki0[4] * u0.y + Ki0[5];
        x0[2] = Ki0[6] * u0.x + Ki0[7] * u0.y + Ki0[8];
        x1[0] = Ki1[0] * u1.x + Ki1[1] * u1.y + Ki1[2];
        x1[1] = Ki1[3] * u1.x + Ki1[4] * u1.y + Ki1[5];
        x1[2] = Ki1[6] * u1.x + Ki1[7] * u1.y + Ki1[8];
#pragma unroll
        for (int i = 0; i < 3; ++i)
#pragma unroll
            for (int j = 0; j < 3; ++j) X[3 * i + j] = x1[i] * x0[j];
#pragma unroll
        for (int i = 0; i < 9; ++i) {
            float wxi = w * X[i];
#pragma unroll
            for (int j = i; j < 9; ++j)
                acc[SU(i, j)] += wxi * X[j];
        }
    }

    __shared__ float red[8][45];
    int lane = threadIdx.x & 31, wid = threadIdx.x >> 5;
#pragma unroll
    for (int m = 0; m < 45; ++m) {
#pragma unroll
        for (int o = 16; o > 0; o >>= 1)
            acc[m] += __shfl_xor_sync(0xffffffffu, acc[m], o);
    }
    if (lane == 0) {
#pragma unroll
        for (int m = 0; m < 45; ++m) red[wid][m] = acc[m];
    }
    __syncthreads();
    if (threadIdx.x < 45) {
        float sum = 0.f;
        int nw = blockDim.x >> 5;
        for (int wd = 0; wd < nw; ++wd) sum += red[wd][threadIdx.x];
        g_Mpart[((size_t)b * SEG + s) * 45 + threadIdx.x] = sum;
    }
}

// ---------------------------------------------------------------------------
// Kernel B: per-thread solve.  Cholesky + inverse iteration for the smallest
// eigenvector of the 9x9 Gram, then closed-form 3x3 SVD -> 4 pose candidates.
// ---------------------------------------------------------------------------
__device__ __forceinline__ void chol9(const float* __restrict__ ms, float shift,
                                      float* __restrict__ L)
{
#pragma unroll
    for (int k = 0; k < 9; ++k) {
        float sdiag = ms[SU(k, k)] - shift;
#pragma unroll
        for (int j = 0; j < k; ++j) sdiag -= L[LT(k, j)] * L[LT(k, j)];
        float d = sqrtf(fmaxf(sdiag, 1e-25f));
        L[LT(k, k)] = d;
        float inv = 1.f / d;
#pragma unroll
        for (int i = k + 1; i < 9; ++i) {
            float t = ASYM(ms, i, k);
#pragma unroll
            for (int j = 0; j < k; ++j) t -= L[LT(i, j)] * L[LT(k, j)];
            L[LT(i, k)] = t * inv;
        }
    }
}

__device__ __forceinline__ void cholsolve9(const float* __restrict__ L,
                                           const float* __restrict__ x,
                                           float* __restrict__ z)
{
    float y[9];
#pragma unroll
    for (int i = 0; i < 9; ++i) {
        float t = x[i];
#pragma unroll
        for (int j = 0; j < i; ++j) t -= L[LT(i, j)] * y[j];
        y[i] = t / L[LT(i, i)];
    }
#pragma unroll
    for (int i = 8; i >= 0; --i) {
        float t = y[i];
#pragma unroll
        for (int j = i + 1; j < 9; ++j) t -= L[LT(j, i)] * z[j];
        z[i] = t / L[LT(i, i)];
    }
}

__global__ __launch_bounds__(32) void k_solve(int B)
{
    int b = blockIdx.x * 32 + threadIdx.x;
    if (b >= B) return;

    // sum the SEG partials
    float ms[45];
#pragma unroll
    for (int m = 0; m < 45; ++m) ms[m] = 0.f;
    for (int s = 0; s < SEG; ++s) {
        const float* p = g_Mpart + ((size_t)b * SEG + s) * 45;
#pragma unroll
        for (int m = 0; m < 45; ++m) ms[m] += p[m];
    }
    // tiny ridge (doesn't change eigenvectors)
    float tr = 0.f;
#pragma unroll
    for (int k = 0; k < 9; ++k) tr += ms[SU(k, k)];
    float eps = 1e-7f * tr;
#pragma unroll
    for (int k = 0; k < 9; ++k) ms[SU(k, k)] += eps;

    float L[45];
    chol9(ms, 0.f, L);

    float v[9];
#pragma unroll
    for (int i = 0; i < 9; ++i) v[i] = 1.f / 3.f;

    float z[9];
#pragma unroll
    for (int it = 0; it < 8; ++it) {
        cholsolve9(L, v, z);
        float nn = 0.f;
#pragma unroll
        for (int i = 0; i < 9; ++i) nn += z[i] * z[i];
        float inv = rsqrtf(nn);
#pragma unroll
        for (int i = 0; i < 9; ++i) v[i] = z[i] * inv;
    }
    // Rayleigh quotient, shift, re-factor, 3 hyper-converged steps
    float Mv[9], rho = 0.f;
#pragma unroll
    for (int i = 0; i < 9; ++i) {
        float t = 0.f;
#pragma unroll
        for (int j = 0; j < 9; ++j) t += ASYM(ms, i, j) * v[j];
        Mv[i] = t;
        rho += v[i] * t;
    }
    chol9(ms, 0.95f * rho, L);
#pragma unroll
    for (int it = 0; it < 3; ++it) {
        cholsolve9(L, v, z);
        float nn = 0.f;
#pragma unroll
        for (int i = 0; i < 9; ++i) nn += z[i] * z[i];
        float inv = rsqrtf(nn);
#pragma unroll
        for (int i = 0; i < 9; ++i) v[i] = z[i] * inv;
    }

    // E = reshape(v, 3, 3)
    float E[3][3];
#pragma unroll
    for (int i = 0; i < 3; ++i)
#pragma unroll
        for (int j = 0; j < 3; ++j) E[i][j] = v[3 * i + j];

    // G = E^T E, 3x3 Jacobi eigendecomposition
    float G[3][3];
#pragma unroll
    for (int i = 0; i < 3; ++i)
#pragma unroll
        for (int j = 0; j < 3; ++j) {
            float s = 0.f;
#pragma unroll
            for (int k = 0; k < 3; ++k) s += E[k][i] * E[k][j];
            G[i][j] = s;
        }
    float ev[3][3] = {{1.f,0.f,0.f},{0.f,1.f,0.f},{0.f,0.f,1.f}};

#define J3(P, Q, R) do {                                                      \
    float app = G[P][P], aqq = G[Q][Q], apq = G[P][Q];                        \
    if (fabsf(apq) > 1e-14f * (fabsf(app) + fabsf(aqq))) {                    \
        float tau = (aqq - app) / (2.f * apq);                                \
        float tt  = copysignf(1.f, tau) / (fabsf(tau) + sqrtf(1.f + tau * tau)); \
        float c   = 1.f / sqrtf(1.f + tt * tt);                               \
        float s   = tt * c;                                                   \
        float apr = G[P][R], aqr = G[Q][R];                                   \
        G[P][P] = app - tt * apq; G[Q][Q] = aqq + tt * apq;                   \
        G[P][Q] = 0.f; G[Q][P] = 0.f;                                         \
        G[P][R] = c * apr - s * aqr; G[R][P] = G[P][R];                       \
        G[Q][R] = s * apr + c * aqr; G[R][Q] = G[Q][R];                       \
        for (int kk = 0; kk < 3; ++kk) {                                      \
            float vp = ev[kk][P], vq = ev[kk][Q];                             \
            ev[kk][P] = c * vp - s * vq;                                      \
            ev[kk][Q] = s * vp + c * vq;                                      \
        }                                                                     \
    } } while (0)

#pragma unroll
    for (int sw = 0; sw < 8; ++sw) { J3(0, 1, 2); J3(0, 2, 1); J3(1, 2, 0); }
#undef J3

    // sort eigenvalues descending
    float l0 = G[0][0], l1 = G[1][1], l2 = G[2][2];
    int i0 = 0, i1 = 1, i2 = 2;
    if (l1 > l0) { float tm = l0; l0 = l1; l1 = tm; int ti = i0; i0 = i1; i1 = ti; }
    if (l2 > l0) { float tm = l0; l0 = l2; l2 = tm; int ti = i0; i0 = i2; i2 = ti; }
    if (l2 > l1) { float tm = l1; l1 = l2; l2 = tm; int ti = i1; i1 = i2; i2 = ti; }

    float v1[3], v2[3], v3[3];
#pragma unroll
    for (int k = 0; k < 3; ++k) { v1[k] = ev[k][i0]; v2[k] = ev[k][i1]; v3[k] = ev[k][i2]; }

    float u1[3], u2[3], u3[3];
#pragma unroll
    for (int i = 0; i < 3; ++i)
        u1[i] = E[i][0] * v1[0] + E[i][1] * v1[1] + E[i][2] * v1[2];
    {
        float nn = rsqrtf(u1[0]*u1[0] + u1[1]*u1[1] + u1[2]*u1[2]);
        u1[0] *= nn; u1[1] *= nn; u1[2] *= nn;
    }
#pragma unroll
    for (int i = 0; i < 3; ++i)
        u2[i] = E[i][0] * v2[0] + E[i][1] * v2[1] + E[i][2] * v2[2];
    {
        float d = u1[0]*u2[0] + u1[1]*u2[1] + u1[2]*u2[2];
        u2[0] -= d * u1[0]; u2[1] -= d * u1[1]; u2[2] -= d * u1[2];
        float nn = rsqrtf(u2[0]*u2[0] + u2[1]*u2[1] + u2[2]*u2[2]);
        u2[0] *= nn; u2[1] *= nn; u2[2] *= nn;
    }
    u3[0] = u1[1] * u2[2] - u1[2] * u2[1];
    u3[1] = u1[2] * u2[0] - u1[0] * u2[2];
    u3[2] = u1[0] * u2[1] - u1[1] * u2[0];

    float Ev3[3];
#pragma unroll
    for (int i = 0; i < 3; ++i)
        Ev3[i] = E[i][0] * v3[0] + E[i][1] * v3[1] + E[i][2] * v3[2];
    float s3p = u3[0]*Ev3[0] + u3[1]*Ev3[1] + u3[2]*Ev3[2];
    if (s3p < 0.f) { v3[0] = -v3[0]; v3[1] = -v3[1]; v3[2] = -v3[2]; }

    float R1[9], R2[9];
#pragma unroll
    for (int i = 0; i < 3; ++i)
#pragma unroll
        for (int j = 0; j < 3; ++j) {
            float c3 = u3[i] * v3[j];
            R1[3 * i + j] =  u2[i] * v1[j] - u1[i] * v2[j] + c3;
            R2[3 * i + j] = -u2[i] * v1[j] + u1[i] * v2[j] + c3;
        }
    float d1 = R1[0]*(R1[4]*R1[8]-R1[5]*R1[7]) - R1[1]*(R1[3]*R1[8]-R1[5]*R1[6]) + R1[2]*(R1[3]*R1[7]-R1[4]*R1[6]);
    float d2 = R2[0]*(R2[4]*R2[8]-R2[5]*R2[7]) - R2[1]*(R2[3]*R2[8]-R2[5]*R2[6]) + R2[2]*(R2[3]*R2[7]-R2[4]*R2[6]);
    float sg1 = (d1 < 0.f) ? -1.f : 1.f;
    float sg2 = (d2 < 0.f) ? -1.f : 1.f;
    float* cd = g_cand + b * 21;
#pragma unroll
    for (int m = 0; m < 9; ++m) { cd[m] = R1[m] * sg1; cd[9 + m] = R2[m] * sg2; }
    cd[18] = u3[0]; cd[19] = u3[1]; cd[20] = u3[2];
}

// ---------------------------------------------------------------------------
// Kernel C: partial cheirality scoring (sign-only; det > 0 so divisions drop)
// ---------------------------------------------------------------------------
__global__ __launch_bounds__(256) void k_score(
    const float* __restrict__ kpts0, const float* __restrict__ kpts1,
    const float* __restrict__ conf,  const float* __restrict__ K, int N)
{
    int b = blockIdx.x;
    int s = blockIdx.y;
    int NS = (N + SEG - 1) / SEG;
    int n0 = s * NS;
    int n1 = min(N, n0 + NS);

    float Ki0[9], Ki1[9];
    inv3x3(K + (size_t)b * 18, Ki0);
    inv3x3(K + (size_t)b * 18 + 9, Ki1);

    const float* cd = g_cand + b * 21;
    float R1[9], R2[9], tv[3];
#pragma unroll
    for (int m = 0; m < 9; ++m) { R1[m] = cd[m]; R2[m] = cd[9 + m]; }
    tv[0] = cd[18]; tv[1] = cd[19]; tv[2] = cd[20];

    const float2* p0 = (const float2*)(kpts0 + (size_t)b * N * 2);
    const float2* p1 = (const float2*)(kpts1 + (size_t)b * N * 2);
    const float*  pw = conf + (size_t)b * N;

    float sc[4] = {0.f, 0.f, 0.f, 0.f};
    for (int n = n0 + threadIdx.x; n < n1; n += blockDim.x) {
        float2 u0 = p0[n];
        float2 u1 = p1[n];
        float  w  = pw[n];
        float x0[3], x1[3];
        x0[0] = Ki0[0] * u0.x + Ki0[1] * u0.y + Ki0[2];
        x0[1] = Ki0[3] * u0.x + Ki0[4] * u0.y + Ki0[5];
        x0[2] = Ki0[6] * u0.x + Ki0[7] * u0.y + Ki0[8];
        x1[0] = Ki1[0] * u1.x + Ki1[1] * u1.y + Ki1[2];
        x1[1] = Ki1[3] * u1.x + Ki1[4] * u1.y + Ki1[5];
        x1[2] = Ki1[6] * u1.x + Ki1[7] * u1.y + Ki1[8];

        float bb = x1[0]*x1[0] + x1[1]*x1[1] + x1[2]*x1[2];
        float bt = x1[0]*tv[0] + x1[1]*tv[1] + x1[2]*tv[2];

        {
            float a0 = R1[0]*x0[0] + R1[1]*x0[1] + R1[2]*x0[2];
            float a1 = R1[3]*x0[0] + R1[4]*x0[1] + R1[5]*x0[2];
            float a2 = R1[6]*x0[0] + R1[7]*x0[1] + R1[8]*x0[2];
            float aa = a0*a0 + a1*a1 + a2*a2;
            float ab = a0*x1[0] + a1*x1[1] + a2*x1[2];
            float at = a0*tv[0] + a1*tv[1] + a2*tv[2];
            float n0v = -at * bb + ab * bt;
            float n1v =  aa * bt - ab * at;
            if (n0v > 0.f && n1v > 0.f) sc[0] += w;
            if (n0v < 0.f && n1v < 0.f) sc[1] += w;
        }
        {
            float a0 = R2[0]*x0[0] + R2[1]*x0[1] + R2[2]*x0[2];
            float a1 = R2[3]*x0[0] + R2[4]*x0[1] + R2[5]*x0[2];
            float a2 = R2[6]*x0[0] + R2[7]*x0[1] + R2[8]*x0[2];
            float aa = a0*a0 + a1*a1 + a2*a2;
            float ab = a0*x1[0] + a1*x1[1] + a2*x1[2];
            float at = a0*tv[0] + a1*tv[1] + a2*tv[2];
            float n0v = -at * bb + ab * bt;
            float n1v =  aa * bt - ab * at;
            if (n0v > 0.f && n1v > 0.f) sc[2] += w;
            if (n0v < 0.f && n1v < 0.f) sc[3] += w;
        }
    }

    __shared__ float red[8][4];
    int lane = threadIdx.x & 31, wid = threadIdx.x >> 5;
#pragma unroll
    for (int m = 0; m < 4; ++m) {
#pragma unroll
        for (int o = 16; o > 0; o >>= 1)
            sc[m] += __shfl_xor_sync(0xffffffffu, sc[m], o);
    }
    if (lane == 0) {
#pragma unroll
        for (int m = 0; m < 4; ++m) red[wid][m] = sc[m];
    }
    __syncthreads();
    if (threadIdx.x < 4) {
        float sum = 0.f;
        int nw = blockDim.x >> 5;
        for (int wd = 0; wd < nw; ++wd) sum += red[wd][threadIdx.x];
        g_sc[((size_t)b * SEG + s) * 4 + threadIdx.x] = sum;
    }
}

// ---------------------------------------------------------------------------
// Kernel D: per-batch argmax + output assembly (T01, T10)
// ---------------------------------------------------------------------------
__global__ __launch_bounds__(128) void k_final(
    const float* __restrict__ tscale, float* __restrict__ out, int B)
{
    int b = blockIdx.x * 128 + threadIdx.x;
    if (b >= B) return;

    float s[4] = {0.f, 0.f, 0.f, 0.f};
    for (int seg = 0; seg < SEG; ++seg) {
        const float* p = g_sc + ((size_t)b * SEG + seg) * 4;
#pragma unroll
        for (int m = 0; m < 4; ++m) s[m] += p[m];
    }
    int best = 0;
    for (int c = 1; c < 4; ++c) if (s[c] > s[best]) best = c;

    const float* cd = g_cand + b * 21;
    float R[9];
    const float* Rs = (best < 2) ? cd : cd + 9;
#pragma unroll
    for (int m = 0; m < 9; ++m) R[m] = Rs[m];
    float sg = (best & 1) ? -1.f : 1.f;
    float ts = tscale[(size_t)b * 2];
    float t0 = sg * cd[18] * ts, t1 = sg * cd[19] * ts, t2 = sg * cd[20] * ts;

    float* o01 = out + (size_t)b * 32;
    float* o10 = o01 + 16;
    o01[0]  = R[0]; o01[1]  = R[1]; o01[2]  = R[2]; o01[3]  = t0;
    o01[4]  = R[3]; o01[5]  = R[4]; o01[6]  = R[5]; o01[7]  = t1;
    o01[8]  = R[6]; o01[9]  = R[7]; o01[10] = R[8]; o01[11] = t2;
    o01[12] = 0.f;  o01[13] = 0.f;  o01[14] = 0.f;  o01[15] = 1.f;
    float ti0 = -(R[0] * t0 + R[3] * t1 + R[6] * t2);
    float ti1 = -(R[1] * t0 + R[4] * t1 + R[7] * t2);
    float ti2 = -(R[2] * t0 + R[5] * t1 + R[8] * t2);
    o10[0]  = R[0]; o10[1]  = R[3]; o10[2]  = R[6]; o10[3]  = ti0;
    o10[4]  = R[1]; o10[5]  = R[4]; o10[6]  = R[7]; o10[7]  = ti1;
    o10[8]  = R[2]; o10[9]  = R[5]; o10[10] = R[8]; o10[11] = ti2;
    o10[12] = 0.f;  o10[13] = 0.f;  o10[14] = 0.f;  o10[15] = 1.f;
}

// ---------------------------------------------------------------------------
extern "C" void kernel_launch(void* const* d_in, const int* in_sizes, int n_in,
                              void* d_out, int out_size)
{
    const float* kpts0 = (const float*)d_in[0];
    const float* kpts1 = (const float*)d_in[1];
    const float* conf  = (const float*)d_in[2];
    const float* tsc   = (const float*)d_in[3];
    const float* K     = (const float*)d_in[4];

    int B = in_sizes[4] / 18;        // K: (B, 2, 3, 3)
    int N = in_sizes[2] / B;         // conf: (B, N, 1)

    dim3 gridA(B, SEG);
    k_accumM<<<gridA, 256>>>(kpts0, kpts1, conf, K, N);
    k_solve<<<(B + 31) / 32, 32>>>(B);
    dim3 gridC(B, SEG);
    k_score<<<gridC, 256>>>(kpts0, kpts1, conf, K, N);
    k_final<<<(B + 127) / 128, 128>>>(tsc, (float*)d_out, B);
}

// round 8
// speedup vs baseline: 1.6767x; 1.6767x over previous
#include <cuda_runtime.h>
#include <math.h>

#define MAXB 2048
#define SEG  4

// scratch (no allocations allowed)
__device__ float g_Mpart[MAXB * SEG * 45];  // per-(batch,seg) Gram upper-tri partials
__device__ float g_cand[MAXB * 21];         // R1(9), R2(9), t(3)
__device__ float g_sc[MAXB * SEG * 4];      // per-(batch,seg) candidate scores
__device__ int   g_cnt[MAXB];               // per-batch done-counter (self-resetting)

__device__ __forceinline__ void inv3x3(const float* __restrict__ K, float* Ki) {
    float a = K[0], b = K[1], c = K[2];
    float d = K[3], e = K[4], f = K[5];
    float g = K[6], h = K[7], i = K[8];
    float A =  (e * i - f * h);
    float Bc = -(d * i - f * g);
    float C =  (d * h - e * g);
    float det = a * A + b * Bc + c * C;
    float id = 1.0f / det;
    Ki[0] = A * id;             Ki[1] = (c * h - b * i) * id; Ki[2] = (b * f - c * e) * id;
    Ki[3] = Bc * id;            Ki[4] = (a * i - c * g) * id; Ki[5] = (c * d - a * f) * id;
    Ki[6] = C * id;             Ki[7] = (b * g - a * h) * id; Ki[8] = (a * e - b * d) * id;
}

// upper-tri index (i <= j), 9x9 -> 45
#define SU(i, j) ((i) * 9 - (i) * ((i) + 1) / 2 + (j))
// lower-tri index (j <= i)
#define LT(i, j) ((i) * ((i) + 1) / 2 + (j))
// symmetric access of ms[45]
#define ASYM(ms, i, j) ((i) <= (j) ? (ms)[SU(i, j)] : (ms)[SU(j, i)])

__device__ __forceinline__ void norm_pt(const float* Ki, float2 u, float* x) {
    x[0] = Ki[0] * u.x + Ki[1] * u.y + Ki[2];
    x[1] = Ki[3] * u.x + Ki[4] * u.y + Ki[5];
    x[2] = Ki[6] * u.x + Ki[7] * u.y + Ki[8];
}

// ---------------------------------------------------------------------------
// Kernel A: partial Gram  M_part(b,s) = sum_{n in seg s} w * X X^T
// 4-wide manual unroll: 12 independent loads up front -> latency paid once.
// ---------------------------------------------------------------------------
__global__ __launch_bounds__(256) void k_accumM(
    const float* __restrict__ kpts0, const float* __restrict__ kpts1,
    const float* __restrict__ conf,  const float* __restrict__ K, int N)
{
    int b = blockIdx.x;
    int s = blockIdx.y;
    int NS = (N + SEG - 1) / SEG;
    int n0 = s * NS;
    int n1 = min(N, n0 + NS);

    float Ki0[9], Ki1[9];
    inv3x3(K + (size_t)b * 18, Ki0);
    inv3x3(K + (size_t)b * 18 + 9, Ki1);

    float acc[45];
#pragma unroll
    for (int m = 0; m < 45; ++m) acc[m] = 0.f;

    const float2* p0 = (const float2*)(kpts0 + (size_t)b * N * 2);
    const float2* p1 = (const float2*)(kpts1 + (size_t)b * N * 2);
    const float*  pw = conf + (size_t)b * N;

    int n = n0 + threadIdx.x;
    // full 4-chunks
    for (; n + 768 < n1; n += 1024) {
        float2 a0[4], a1[4];
        float  w[4];
#pragma unroll
        for (int k = 0; k < 4; ++k) {
            a0[k] = p0[n + k * 256];
            a1[k] = p1[n + k * 256];
            w[k]  = pw[n + k * 256];
        }
#pragma unroll
        for (int k = 0; k < 4; ++k) {
            float x0[3], x1[3], X[9];
            norm_pt(Ki0, a0[k], x0);
            norm_pt(Ki1, a1[k], x1);
#pragma unroll
            for (int i = 0; i < 3; ++i)
#pragma unroll
                for (int j = 0; j < 3; ++j) X[3 * i + j] = x1[i] * x0[j];
#pragma unroll
            for (int i = 0; i < 9; ++i) {
                float wxi = w[k] * X[i];
#pragma unroll
                for (int j = i; j < 9; ++j)
                    acc[SU(i, j)] += wxi * X[j];
            }
        }
    }
    // remainder
    for (; n < n1; n += 256) {
        float2 u0 = p0[n];
        float2 u1 = p1[n];
        float  w  = pw[n];
        float x0[3], x1[3], X[9];
        norm_pt(Ki0, u0, x0);
        norm_pt(Ki1, u1, x1);
#pragma unroll
        for (int i = 0; i < 3; ++i)
#pragma unroll
            for (int j = 0; j < 3; ++j) X[3 * i + j] = x1[i] * x0[j];
#pragma unroll
        for (int i = 0; i < 9; ++i) {
            float wxi = w * X[i];
#pragma unroll
            for (int j = i; j < 9; ++j)
                acc[SU(i, j)] += wxi * X[j];
        }
    }

    __shared__ float red[8][45];
    int lane = threadIdx.x & 31, wid = threadIdx.x >> 5;
#pragma unroll
    for (int m = 0; m < 45; ++m) {
#pragma unroll
        for (int o = 16; o > 0; o >>= 1)
            acc[m] += __shfl_xor_sync(0xffffffffu, acc[m], o);
    }
    if (lane == 0) {
#pragma unroll
        for (int m = 0; m < 45; ++m) red[wid][m] = acc[m];
    }
    __syncthreads();
    if (threadIdx.x < 45) {
        float sum = 0.f;
        int nw = blockDim.x >> 5;
        for (int wd = 0; wd < nw; ++wd) sum += red[wd][threadIdx.x];
        g_Mpart[((size_t)b * SEG + s) * 45 + threadIdx.x] = sum;
    }
}

// ---------------------------------------------------------------------------
// Kernel B: per-thread solve. Cholesky + inverse iteration for the smallest
// eigenvector of the 9x9 Gram, then 3x3 SVD -> 4 pose candidates.
// ---------------------------------------------------------------------------
__device__ __forceinline__ void chol9(const float* __restrict__ ms, float shift,
                                      float* __restrict__ L, float* __restrict__ invd)
{
#pragma unroll
    for (int k = 0; k < 9; ++k) {
        float sdiag = ms[SU(k, k)] - shift;
#pragma unroll
        for (int j = 0; j < k; ++j) sdiag -= L[LT(k, j)] * L[LT(k, j)];
        float d = sqrtf(fmaxf(sdiag, 1e-25f));
        L[LT(k, k)] = d;
        float inv = 1.f / d;
        invd[k] = inv;
#pragma unroll
        for (int i = k + 1; i < 9; ++i) {
            float t = ASYM(ms, i, k);
#pragma unroll
            for (int j = 0; j < k; ++j) t -= L[LT(i, j)] * L[LT(k, j)];
            L[LT(i, k)] = t * inv;
        }
    }
}

__device__ __forceinline__ void cholsolve9(const float* __restrict__ L,
                                           const float* __restrict__ invd,
                                           const float* __restrict__ x,
                                           float* __restrict__ z)
{
    float y[9];
#pragma unroll
    for (int i = 0; i < 9; ++i) {
        float t = x[i];
#pragma unroll
        for (int j = 0; j < i; ++j) t -= L[LT(i, j)] * y[j];
        y[i] = t * invd[i];
    }
#pragma unroll
    for (int i = 8; i >= 0; --i) {
        float t = y[i];
#pragma unroll
        for (int j = i + 1; j < 9; ++j) t -= L[LT(j, i)] * z[j];
        z[i] = t * invd[i];
    }
}

__global__ __launch_bounds__(64) void k_solve(int B)
{
    int b = blockIdx.x * 64 + threadIdx.x;
    if (b >= B) return;

    float ms[45];
#pragma unroll
    for (int m = 0; m < 45; ++m) ms[m] = 0.f;
#pragma unroll
    for (int s = 0; s < SEG; ++s) {
        const float* p = g_Mpart + ((size_t)b * SEG + s) * 45;
#pragma unroll
        for (int m = 0; m < 45; ++m) ms[m] += p[m];
    }
    float tr = 0.f;
#pragma unroll
    for (int k = 0; k < 9; ++k) tr += ms[SU(k, k)];
    float eps = 1e-7f * tr;
#pragma unroll
    for (int k = 0; k < 9; ++k) ms[SU(k, k)] += eps;

    float L[45], invd[9];
    chol9(ms, 0.f, L, invd);

    float v[9];
#pragma unroll
    for (int i = 0; i < 9; ++i) v[i] = 1.f / 3.f;

    float z[9];
#pragma unroll
    for (int it = 0; it < 8; ++it) {   // 8 steps: proven sufficient (R4)
        cholsolve9(L, invd, v, z);
        float nn = 0.f;
#pragma unroll
        for (int i = 0; i < 9; ++i) nn += z[i] * z[i];
        float inv = rsqrtf(nn);
#pragma unroll
        for (int i = 0; i < 9; ++i) v[i] = z[i] * inv;
    }
    // Rayleigh shift + 3 hyper-converged steps
    float rho = 0.f;
#pragma unroll
    for (int i = 0; i < 9; ++i) {
        float t = 0.f;
#pragma unroll
        for (int j = 0; j < 9; ++j) t += ASYM(ms, i, j) * v[j];
        rho += v[i] * t;
    }
    chol9(ms, 0.95f * rho, L, invd);
#pragma unroll
    for (int it = 0; it < 3; ++it) {
        cholsolve9(L, invd, v, z);
        float nn = 0.f;
#pragma unroll
        for (int i = 0; i < 9; ++i) nn += z[i] * z[i];
        float inv = rsqrtf(nn);
#pragma unroll
        for (int i = 0; i < 9; ++i) v[i] = z[i] * inv;
    }

    float E[3][3];
#pragma unroll
    for (int i = 0; i < 3; ++i)
#pragma unroll
        for (int j = 0; j < 3; ++j) E[i][j] = v[3 * i + j];

    float G[3][3];
#pragma unroll
    for (int i = 0; i < 3; ++i)
#pragma unroll
        for (int j = 0; j < 3; ++j) {
            float s = 0.f;
#pragma unroll
            for (int k = 0; k < 3; ++k) s += E[k][i] * E[k][j];
            G[i][j] = s;
        }
    float ev[3][3] = {{1.f,0.f,0.f},{0.f,1.f,0.f},{0.f,0.f,1.f}};

#define J3(P, Q, R) do {                                                      \
    float app = G[P][P], aqq = G[Q][Q], apq = G[P][Q];                        \
    if (fabsf(apq) > 1e-14f * (fabsf(app) + fabsf(aqq))) {                    \
        float tau = (aqq - app) / (2.f * apq);                                \
        float tt  = copysignf(1.f, tau) / (fabsf(tau) + sqrtf(1.f + tau * tau)); \
        float c   = 1.f / sqrtf(1.f + tt * tt);                               \
        float s   = tt * c;                                                   \
        float apr = G[P][R], aqr = G[Q][R];                                   \
        G[P][P] = app - tt * apq; G[Q][Q] = aqq + tt * apq;                   \
        G[P][Q] = 0.f; G[Q][P] = 0.f;                                         \
        G[P][R] = c * apr - s * aqr; G[R][P] = G[P][R];                       \
        G[Q][R] = s * apr + c * aqr; G[R][Q] = G[Q][R];                       \
        for (int kk = 0; kk < 3; ++kk) {                                      \
            float vp = ev[kk][P], vq = ev[kk][Q];                             \
            ev[kk][P] = c * vp - s * vq;                                      \
            ev[kk][Q] = s * vp + c * vq;                                      \
        }                                                                     \
    } } while (0)

#pragma unroll
    for (int sw = 0; sw < 8; ++sw) { J3(0, 1, 2); J3(0, 2, 1); J3(1, 2, 0); }
#undef J3

    float l0 = G[0][0], l1 = G[1][1], l2 = G[2][2];
    int i0 = 0, i1 = 1, i2 = 2;
    if (l1 > l0) { float tm = l0; l0 = l1; l1 = tm; int ti = i0; i0 = i1; i1 = ti; }
    if (l2 > l0) { float tm = l0; l0 = l2; l2 = tm; int ti = i0; i0 = i2; i2 = ti; }
    if (l2 > l1) { float tm = l1; l1 = l2; l2 = tm; int ti = i1; i1 = i2; i2 = ti; }

    float v1[3], v2[3], v3[3];
#pragma unroll
    for (int k = 0; k < 3; ++k) { v1[k] = ev[k][i0]; v2[k] = ev[k][i1]; v3[k] = ev[k][i2]; }

    float u1[3], u2[3], u3[3];
#pragma unroll
    for (int i = 0; i < 3; ++i)
        u1[i] = E[i][0] * v1[0] + E[i][1] * v1[1] + E[i][2] * v1[2];
    {
        float nn = rsqrtf(u1[0]*u1[0] + u1[1]*u1[1] + u1[2]*u1[2]);
        u1[0] *= nn; u1[1] *= nn; u1[2] *= nn;
    }
#pragma unroll
    for (int i = 0; i < 3; ++i)
        u2[i] = E[i][0] * v2[0] + E[i][1] * v2[1] + E[i][2] * v2[2];
    {
        float d = u1[0]*u2[0] + u1[1]*u2[1] + u1[2]*u2[2];
        u2[0] -= d * u1[0]; u2[1] -= d * u1[1]; u2[2] -= d * u1[2];
        float nn = rsqrtf(u2[0]*u2[0] + u2[1]*u2[1] + u2[2]*u2[2]);
        u2[0] *= nn; u2[1] *= nn; u2[2] *= nn;
    }
    u3[0] = u1[1] * u2[2] - u1[2] * u2[1];
    u3[1] = u1[2] * u2[0] - u1[0] * u2[2];
    u3[2] = u1[0] * u2[1] - u1[1] * u2[0];

    float Ev3[3];
#pragma unroll
    for (int i = 0; i < 3; ++i)
        Ev3[i] = E[i][0] * v3[0] + E[i][1] * v3[1] + E[i][2] * v3[2];
    float s3p = u3[0]*Ev3[0] + u3[1]*Ev3[1] + u3[2]*Ev3[2];
    if (s3p < 0.f) { v3[0] = -v3[0]; v3[1] = -v3[1]; v3[2] = -v3[2]; }

    float R1[9], R2[9];
#pragma unroll
    for (int i = 0; i < 3; ++i)
#pragma unroll
        for (int j = 0; j < 3; ++j) {
            float c3 = u3[i] * v3[j];
            R1[3 * i + j] =  u2[i] * v1[j] - u1[i] * v2[j] + c3;
            R2[3 * i + j] = -u2[i] * v1[j] + u1[i] * v2[j] + c3;
        }
    float d1 = R1[0]*(R1[4]*R1[8]-R1[5]*R1[7]) - R1[1]*(R1[3]*R1[8]-R1[5]*R1[6]) + R1[2]*(R1[3]*R1[7]-R1[4]*R1[6]);
    float d2 = R2[0]*(R2[4]*R2[8]-R2[5]*R2[7]) - R2[1]*(R2[3]*R2[8]-R2[5]*R2[6]) + R2[2]*(R2[3]*R2[7]-R2[4]*R2[6]);
    float sg1 = (d1 < 0.f) ? -1.f : 1.f;
    float sg2 = (d2 < 0.f) ? -1.f : 1.f;
    float* cd = g_cand + b * 21;
#pragma unroll
    for (int m = 0; m < 9; ++m) { cd[m] = R1[m] * sg1; cd[9 + m] = R2[m] * sg2; }
    cd[18] = u3[0]; cd[19] = u3[1]; cd[20] = u3[2];
}

// ---------------------------------------------------------------------------
// Kernel C: partial cheirality scoring + fused last-block finalize
// ---------------------------------------------------------------------------
__device__ __forceinline__ void score_pt(
    const float* R1, const float* R2, const float* tv,
    const float* x0, const float* x1, float w, float* sc)
{
    float bb = x1[0]*x1[0] + x1[1]*x1[1] + x1[2]*x1[2];
    float bt = x1[0]*tv[0] + x1[1]*tv[1] + x1[2]*tv[2];
    {
        float a0 = R1[0]*x0[0] + R1[1]*x0[1] + R1[2]*x0[2];
        float a1 = R1[3]*x0[0] + R1[4]*x0[1] + R1[5]*x0[2];
        float a2 = R1[6]*x0[0] + R1[7]*x0[1] + R1[8]*x0[2];
        float aa = a0*a0 + a1*a1 + a2*a2;
        float ab = a0*x1[0] + a1*x1[1] + a2*x1[2];
        float at = a0*tv[0] + a1*tv[1] + a2*tv[2];
        float n0v = -at * bb + ab * bt;
        float n1v =  aa * bt - ab * at;
        if (n0v > 0.f && n1v > 0.f) sc[0] += w;
        if (n0v < 0.f && n1v < 0.f) sc[1] += w;
    }
    {
        float a0 = R2[0]*x0[0] + R2[1]*x0[1] + R2[2]*x0[2];
        float a1 = R2[3]*x0[0] + R2[4]*x0[1] + R2[5]*x0[2];
        float a2 = R2[6]*x0[0] + R2[7]*x0[1] + R2[8]*x0[2];
        float aa = a0*a0 + a1*a1 + a2*a2;
        float ab = a0*x1[0] + a1*x1[1] + a2*x1[2];
        float at = a0*tv[0] + a1*tv[1] + a2*tv[2];
        float n0v = -at * bb + ab * bt;
        float n1v =  aa * bt - ab * at;
        if (n0v > 0.f && n1v > 0.f) sc[2] += w;
        if (n0v < 0.f && n1v < 0.f) sc[3] += w;
    }
}

__global__ __launch_bounds__(256) void k_score(
    const float* __restrict__ kpts0, const float* __restrict__ kpts1,
    const float* __restrict__ conf,  const float* __restrict__ tscale,
    const float* __restrict__ K, float* __restrict__ out, int N)
{
    int b = blockIdx.x;
    int s = blockIdx.y;
    int NS = (N + SEG - 1) / SEG;
    int n0 = s * NS;
    int n1 = min(N, n0 + NS);

    float Ki0[9], Ki1[9];
    inv3x3(K + (size_t)b * 18, Ki0);
    inv3x3(K + (size_t)b * 18 + 9, Ki1);

    const float* cd = g_cand + b * 21;
    float R1[9], R2[9], tv[3];
#pragma unroll
    for (int m = 0; m < 9; ++m) { R1[m] = cd[m]; R2[m] = cd[9 + m]; }
    tv[0] = cd[18]; tv[1] = cd[19]; tv[2] = cd[20];

    const float2* p0 = (const float2*)(kpts0 + (size_t)b * N * 2);
    const float2* p1 = (const float2*)(kpts1 + (size_t)b * N * 2);
    const float*  pw = conf + (size_t)b * N;

    float sc[4] = {0.f, 0.f, 0.f, 0.f};
    int n = n0 + threadIdx.x;
    for (; n + 768 < n1; n += 1024) {
        float2 a0[4], a1[4];
        float  w[4];
#pragma unroll
        for (int k = 0; k < 4; ++k) {
            a0[k] = p0[n + k * 256];
            a1[k] = p1[n + k * 256];
            w[k]  = pw[n + k * 256];
        }
#pragma unroll
        for (int k = 0; k < 4; ++k) {
            float x0[3], x1[3];
            norm_pt(Ki0, a0[k], x0);
            norm_pt(Ki1, a1[k], x1);
            score_pt(R1, R2, tv, x0, x1, w[k], sc);
        }
    }
    for (; n < n1; n += 256) {
        float2 u0 = p0[n];
        float2 u1 = p1[n];
        float  w  = pw[n];
        float x0[3], x1[3];
        norm_pt(Ki0, u0, x0);
        norm_pt(Ki1, u1, x1);
        score_pt(R1, R2, tv, x0, x1, w, sc);
    }

    __shared__ float red[8][4];
    __shared__ bool amLast;
    int lane = threadIdx.x & 31, wid = threadIdx.x >> 5;
#pragma unroll
    for (int m = 0; m < 4; ++m) {
#pragma unroll
        for (int o = 16; o > 0; o >>= 1)
            sc[m] += __shfl_xor_sync(0xffffffffu, sc[m], o);
    }
    if (lane == 0) {
#pragma unroll
        for (int m = 0; m < 4; ++m) red[wid][m] = sc[m];
    }
    __syncthreads();

    if (threadIdx.x == 0) {
        float part[4];
        int nw = blockDim.x >> 5;
#pragma unroll
        for (int m = 0; m < 4; ++m) {
            float sum = 0.f;
            for (int wd = 0; wd < nw; ++wd) sum += red[wd][m];
            part[m] = sum;
        }
        float* dst = g_sc + ((size_t)b * SEG + s) * 4;
#pragma unroll
        for (int m = 0; m < 4; ++m) dst[m] = part[m];
        __threadfence();
        int prev = atomicAdd(&g_cnt[b], 1);
        amLast = (prev == SEG - 1);
    }
    __syncthreads();

    if (amLast && threadIdx.x == 0) {
        __threadfence();
        // deterministic fixed-order sum over segments
        float stot[4] = {0.f, 0.f, 0.f, 0.f};
        for (int seg = 0; seg < SEG; ++seg) {
            const float* p = g_sc + ((size_t)b * SEG + seg) * 4;
#pragma unroll
            for (int m = 0; m < 4; ++m) stot[m] += p[m];
        }
        int best = 0;
        for (int c = 1; c < 4; ++c) if (stot[c] > stot[best]) best = c;

        float R[9];
        const float* Rs = (best < 2) ? R1 : R2;
#pragma unroll
        for (int m = 0; m < 9; ++m) R[m] = Rs[m];
        float sg = (best & 1) ? -1.f : 1.f;
        float ts = tscale[(size_t)b * 2];
        float t0 = sg * tv[0] * ts, t1 = sg * tv[1] * ts, t2 = sg * tv[2] * ts;

        float* o01 = out + (size_t)b * 32;
        float* o10 = o01 + 16;
        o01[0]  = R[0]; o01[1]  = R[1]; o01[2]  = R[2]; o01[3]  = t0;
        o01[4]  = R[3]; o01[5]  = R[4]; o01[6]  = R[5]; o01[7]  = t1;
        o01[8]  = R[6]; o01[9]  = R[7]; o01[10] = R[8]; o01[11] = t2;
        o01[12] = 0.f;  o01[13] = 0.f;  o01[14] = 0.f;  o01[15] = 1.f;
        float ti0 = -(R[0] * t0 + R[3] * t1 + R[6] * t2);
        float ti1 = -(R[1] * t0 + R[4] * t1 + R[7] * t2);
        float ti2 = -(R[2] * t0 + R[5] * t1 + R[8] * t2);
        o10[0]  = R[0]; o10[1]  = R[3]; o10[2]  = R[6]; o10[3]  = ti0;
        o10[4]  = R[1]; o10[5]  = R[4]; o10[6]  = R[7]; o10[7]  = ti1;
        o10[8]  = R[2]; o10[9]  = R[5]; o10[10] = R[8]; o10[11] = ti2;
        o10[12] = 0.f;  o10[13] = 0.f;  o10[14] = 0.f;  o10[15] = 1.f;

        g_cnt[b] = 0;   // reset for next graph replay
    }
}

// ---------------------------------------------------------------------------
extern "C" void kernel_launch(void* const* d_in, const int* in_sizes, int n_in,
                              void* d_out, int out_size)
{
    const float* kpts0 = (const float*)d_in[0];
    const float* kpts1 = (const float*)d_in[1];
    const float* conf  = (const float*)d_in[2];
    const float* tsc   = (const float*)d_in[3];
    const float* K     = (const float*)d_in[4];

    int B = in_sizes[4] / 18;        // K: (B, 2, 3, 3)
    int N = in_sizes[2] / B;         // conf: (B, N, 1)

    dim3 gridA(B, SEG);
    k_accumM<<<gridA, 256>>>(kpts0, kpts1, conf, K, N);
    k_solve<<<(B + 63) / 64, 64>>>(B);
    dim3 gridC(B, SEG);
    k_score<<<gridC, 256>>>(kpts0, kpts1, conf, tsc, K, (float*)d_out, N);
}

// round 9
// speedup vs baseline: 1.8918x; 1.1283x over previous
#include <cuda_runtime.h>
#include <math.h>

#define MAXB 2048
#define SEGA 2   // segments for Gram accumulation
#define SEGS 4   // segments for scoring

// scratch (no allocations allowed)
__device__ float g_Mpart[MAXB * SEGA * 36];  // per-(batch,seg) 6x6 moment partials
__device__ float g_cand[MAXB * 21];          // R1(9), R2(9), t(3)
__device__ float g_sc[MAXB * SEGS * 4];      // per-(batch,seg) candidate scores
__device__ int   g_cnt[MAXB];                // per-batch done-counter (self-resetting)

__device__ __forceinline__ void inv3x3(const float* __restrict__ K, float* Ki) {
    float a = K[0], b = K[1], c = K[2];
    float d = K[3], e = K[4], f = K[5];
    float g = K[6], h = K[7], i = K[8];
    float A =  (e * i - f * h);
    float Bc = -(d * i - f * g);
    float C =  (d * h - e * g);
    float det = a * A + b * Bc + c * C;
    float id = 1.0f / det;
    Ki[0] = A * id;             Ki[1] = (c * h - b * i) * id; Ki[2] = (b * f - c * e) * id;
    Ki[3] = Bc * id;            Ki[4] = (a * i - c * g) * id; Ki[5] = (c * d - a * f) * id;
    Ki[6] = C * id;             Ki[7] = (b * g - a * h) * id; Ki[8] = (a * e - b * d) * id;
}

// upper-tri index (i <= j), 9x9 -> 45
#define SU(i, j) ((i) * 9 - (i) * ((i) + 1) / 2 + (j))
// lower-tri index (j <= i)
#define LT(i, j) ((i) * ((i) + 1) / 2 + (j))
// symmetric access of ms[45]
#define ASYM(ms, i, j) ((i) <= (j) ? (ms)[SU(i, j)] : (ms)[SU(j, i)])
// 3x3 symmetric pair index (i <= k): (0,0)->0 (0,1)->1 (0,2)->2 (1,1)->3 (1,2)->4 (2,2)->5
#define S3(i, k) ((i) * (5 - (i)) / 2 + (k))

// ---------------------------------------------------------------------------
// Kernel A: partial moments  A[a][b] = sum_n (w * P_a) * Q_b
//           P = upper(x1 x1^T)  (6),  Q = upper(x0 x0^T)  (6)
// ---------------------------------------------------------------------------
__global__ __launch_bounds__(256) void k_accumM(
    const float* __restrict__ kpts0, const float* __restrict__ kpts1,
    const float* __restrict__ conf,  const float* __restrict__ K, int N)
{
    int b = blockIdx.x;
    int s = blockIdx.y;
    int NS = (N + SEGA - 1) / SEGA;
    int n0 = s * NS;
    int n1 = min(N, n0 + NS);

    float Ki0[9], Ki1[9];
    inv3x3(K + (size_t)b * 18, Ki0);
    inv3x3(K + (size_t)b * 18 + 9, Ki1);

    float acc[36];
#pragma unroll
    for (int m = 0; m < 36; ++m) acc[m] = 0.f;

    const float4* p0v = (const float4*)(kpts0 + (size_t)b * N * 2);
    const float4* p1v = (const float4*)(kpts1 + (size_t)b * N * 2);
    const float4* pwv = (const float4*)(conf  + (size_t)b * N);
    const float2* p0  = (const float2*)(kpts0 + (size_t)b * N * 2);
    const float2* p1  = (const float2*)(kpts1 + (size_t)b * N * 2);
    const float*  pw  = conf + (size_t)b * N;

    auto do_pt = [&](float ux0, float uy0, float ux1, float uy1, float w) {
        float x00 = fmaf(Ki0[0], ux0, fmaf(Ki0[1], uy0, Ki0[2]));
        float x01 = fmaf(Ki0[3], ux0, fmaf(Ki0[4], uy0, Ki0[5]));
        float x02 = fmaf(Ki0[6], ux0, fmaf(Ki0[7], uy0, Ki0[8]));
        float x10 = fmaf(Ki1[0], ux1, fmaf(Ki1[1], uy1, Ki1[2]));
        float x11 = fmaf(Ki1[3], ux1, fmaf(Ki1[4], uy1, Ki1[5]));
        float x12 = fmaf(Ki1[6], ux1, fmaf(Ki1[7], uy1, Ki1[8]));
        float P[6], Q[6];
        P[0] = x10 * x10; P[1] = x10 * x11; P[2] = x10 * x12;
        P[3] = x11 * x11; P[4] = x11 * x12; P[5] = x12 * x12;
        Q[0] = x00 * x00; Q[1] = x00 * x01; Q[2] = x00 * x02;
        Q[3] = x01 * x01; Q[4] = x01 * x02; Q[5] = x02 * x02;
#pragma unroll
        for (int a = 0; a < 6; ++a) {
            float t = w * P[a];
#pragma unroll
            for (int q = 0; q < 6; ++q)
                acc[a * 6 + q] = fmaf(t, Q[q], acc[a * 6 + q]);
        }
    };

    // vectorized 8-points-per-thread loop (covers the largest 2048-multiple span)
    int span = n1 - n0;
    int nvec = n0 + (span / 2048) * 2048;
    for (int base = n0 + threadIdx.x * 8; base + 8 <= nvec; base += 2048) {
        float4 a0[4], a1[4], wv[2];
        int h = base >> 1;
#pragma unroll
        for (int k = 0; k < 4; ++k) { a0[k] = p0v[h + k]; a1[k] = p1v[h + k]; }
        wv[0] = pwv[base >> 2];
        wv[1] = pwv[(base >> 2) + 1];
        const float* wf = (const float*)wv;
#pragma unroll
        for (int j = 0; j < 8; ++j) {
            float ux0 = (j & 1) ? a0[j >> 1].z : a0[j >> 1].x;
            float uy0 = (j & 1) ? a0[j >> 1].w : a0[j >> 1].y;
            float ux1 = (j & 1) ? a1[j >> 1].z : a1[j >> 1].x;
            float uy1 = (j & 1) ? a1[j >> 1].w : a1[j >> 1].y;
            do_pt(ux0, uy0, ux1, uy1, wf[j]);
        }
    }
    // scalar tail
    for (int n = nvec + threadIdx.x; n < n1; n += 256) {
        float2 u0 = p0[n];
        float2 u1 = p1[n];
        do_pt(u0.x, u0.y, u1.x, u1.y, pw[n]);
    }

    // block reduction of 36 values
    __shared__ float red[8][36];
    int lane = threadIdx.x & 31, wid = threadIdx.x >> 5;
#pragma unroll
    for (int m = 0; m < 36; ++m) {
#pragma unroll
        for (int o = 16; o > 0; o >>= 1)
            acc[m] += __shfl_xor_sync(0xffffffffu, acc[m], o);
    }
    if (lane == 0) {
#pragma unroll
        for (int m = 0; m < 36; ++m) red[wid][m] = acc[m];
    }
    __syncthreads();
    if (threadIdx.x < 36) {
        float sum = 0.f;
        int nw = blockDim.x >> 5;
        for (int wd = 0; wd < nw; ++wd) sum += red[wd][threadIdx.x];
        g_Mpart[((size_t)b * SEGA + s) * 36 + threadIdx.x] = sum;
    }
}

// ---------------------------------------------------------------------------
// Kernel B: per-thread solve. Cholesky + inverse iteration for the smallest
// eigenvector of the 9x9 Gram, then 3x3 SVD -> 4 pose candidates.
// ---------------------------------------------------------------------------
__device__ __forceinline__ void chol9(const float* __restrict__ ms, float shift,
                                      float* __restrict__ L, float* __restrict__ invd)
{
#pragma unroll
    for (int k = 0; k < 9; ++k) {
        float sdiag = ms[SU(k, k)] - shift;
#pragma unroll
        for (int j = 0; j < k; ++j) sdiag -= L[LT(k, j)] * L[LT(k, j)];
        float d = sqrtf(fmaxf(sdiag, 1e-25f));
        L[LT(k, k)] = d;
        float inv = 1.f / d;
        invd[k] = inv;
#pragma unroll
        for (int i = k + 1; i < 9; ++i) {
            float t = ASYM(ms, i, k);
#pragma unroll
            for (int j = 0; j < k; ++j) t -= L[LT(i, j)] * L[LT(k, j)];
            L[LT(i, k)] = t * inv;
        }
    }
}

__device__ __forceinline__ void cholsolve9(const float* __restrict__ L,
                                           const float* __restrict__ invd,
                                           const float* __restrict__ x,
                                           float* __restrict__ z)
{
    float y[9];
#pragma unroll
    for (int i = 0; i < 9; ++i) {
        float t = x[i];
#pragma unroll
        for (int j = 0; j < i; ++j) t -= L[LT(i, j)] * y[j];
        y[i] = t * invd[i];
    }
#pragma unroll
    for (int i = 8; i >= 0; --i) {
        float t = y[i];
#pragma unroll
        for (int j = i + 1; j < 9; ++j) t -= L[LT(j, i)] * z[j];
        z[i] = t * invd[i];
    }
}

__global__ __launch_bounds__(64) void k_solve(int B)
{
    int b = blockIdx.x * 64 + threadIdx.x;
    if (b >= B) return;

    // sum the SEGA moment partials
    float A36[36];
#pragma unroll
    for (int m = 0; m < 36; ++m) A36[m] = 0.f;
#pragma unroll
    for (int s = 0; s < SEGA; ++s) {
        const float* p = g_Mpart + ((size_t)b * SEGA + s) * 36;
#pragma unroll
        for (int m = 0; m < 36; ++m) A36[m] += p[m];
    }

    // rebuild 9x9 Gram upper triangle: M_(3i+j)(3k+l) = A[S3(i,k)][S3(j,l)]
    float ms[45];
#pragma unroll
    for (int r = 0; r < 9; ++r) {
        const int i = r / 3, j = r % 3;
#pragma unroll
        for (int c = 0; c < 9; ++c) {
            if (c < r) continue;
            const int k = c / 3, l = c % 3;
            const int jj = (j < l) ? j : l;
            const int ll = (j < l) ? l : j;
            ms[SU(r, c)] = A36[S3(i, k) * 6 + S3(jj, ll)];
        }
    }

    float tr = 0.f;
#pragma unroll
    for (int k = 0; k < 9; ++k) tr += ms[SU(k, k)];
    float eps = 1e-7f * tr;
#pragma unroll
    for (int k = 0; k < 9; ++k) ms[SU(k, k)] += eps;

    float L[45], invd[9];
    chol9(ms, 0.f, L, invd);

    float v[9];
#pragma unroll
    for (int i = 0; i < 9; ++i) v[i] = 1.f / 3.f;

    float z[9];
#pragma unroll
    for (int it = 0; it < 8; ++it) {   // 8 steps: proven sufficient
        cholsolve9(L, invd, v, z);
        float nn = 0.f;
#pragma unroll
        for (int i = 0; i < 9; ++i) nn += z[i] * z[i];
        float inv = rsqrtf(nn);
#pragma unroll
        for (int i = 0; i < 9; ++i) v[i] = z[i] * inv;
    }
    // Rayleigh shift + 3 hyper-converged steps
    float rho = 0.f;
#pragma unroll
    for (int i = 0; i < 9; ++i) {
        float t = 0.f;
#pragma unroll
        for (int j = 0; j < 9; ++j) t += ASYM(ms, i, j) * v[j];
        rho += v[i] * t;
    }
    chol9(ms, 0.95f * rho, L, invd);
#pragma unroll
    for (int it = 0; it < 3; ++it) {
        cholsolve9(L, invd, v, z);
        float nn = 0.f;
#pragma unroll
        for (int i = 0; i < 9; ++i) nn += z[i] * z[i];
        float inv = rsqrtf(nn);
#pragma unroll
        for (int i = 0; i < 9; ++i) v[i] = z[i] * inv;
    }

    float E[3][3];
#pragma unroll
    for (int i = 0; i < 3; ++i)
#pragma unroll
        for (int j = 0; j < 3; ++j) E[i][j] = v[3 * i + j];

    float G[3][3];
#pragma unroll
    for (int i = 0; i < 3; ++i)
#pragma unroll
        for (int j = 0; j < 3; ++j) {
            float s = 0.f;
#pragma unroll
            for (int k = 0; k < 3; ++k) s += E[k][i] * E[k][j];
            G[i][j] = s;
        }
    float ev[3][3] = {{1.f,0.f,0.f},{0.f,1.f,0.f},{0.f,0.f,1.f}};

#define J3(P, Q, R) do {                                                      \
    float app = G[P][P], aqq = G[Q][Q], apq = G[P][Q];                        \
    if (fabsf(apq) > 1e-14f * (fabsf(app) + fabsf(aqq))) {                    \
        float tau = (aqq - app) / (2.f * apq);                                \
        float tt  = copysignf(1.f, tau) / (fabsf(tau) + sqrtf(1.f + tau * tau)); \
        float c   = 1.f / sqrtf(1.f + tt * tt);                               \
        float s   = tt * c;                                                   \
        float apr = G[P][R], aqr = G[Q][R];                                   \
        G[P][P] = app - tt * apq; G[Q][Q] = aqq + tt * apq;                   \
        G[P][Q] = 0.f; G[Q][P] = 0.f;                                         \
        G[P][R] = c * apr - s * aqr; G[R][P] = G[P][R];                       \
        G[Q][R] = s * apr + c * aqr; G[R][Q] = G[Q][R];                       \
        for (int kk = 0; kk < 3; ++kk) {                                      \
            float vp = ev[kk][P], vq = ev[kk][Q];                             \
            ev[kk][P] = c * vp - s * vq;                                      \
            ev[kk][Q] = s * vp + c * vq;                                      \
        }                                                                     \
    } } while (0)

#pragma unroll
    for (int sw = 0; sw < 8; ++sw) { J3(0, 1, 2); J3(0, 2, 1); J3(1, 2, 0); }
#undef J3

    float l0 = G[0][0], l1 = G[1][1], l2 = G[2][2];
    int i0 = 0, i1 = 1, i2 = 2;
    if (l1 > l0) { float tm = l0; l0 = l1; l1 = tm; int ti = i0; i0 = i1; i1 = ti; }
    if (l2 > l0) { float tm = l0; l0 = l2; l2 = tm; int ti = i0; i0 = i2; i2 = ti; }
    if (l2 > l1) { float tm = l1; l1 = l2; l2 = tm; int ti = i1; i1 = i2; i2 = ti; }

    float v1[3], v2[3], v3[3];
#pragma unroll
    for (int k = 0; k < 3; ++k) { v1[k] = ev[k][i0]; v2[k] = ev[k][i1]; v3[k] = ev[k][i2]; }

    float u1[3], u2[3], u3[3];
#pragma unroll
    for (int i = 0; i < 3; ++i)
        u1[i] = E[i][0] * v1[0] + E[i][1] * v1[1] + E[i][2] * v1[2];
    {
        float nn = rsqrtf(u1[0]*u1[0] + u1[1]*u1[1] + u1[2]*u1[2]);
        u1[0] *= nn; u1[1] *= nn; u1[2] *= nn;
    }
#pragma unroll
    for (int i = 0; i < 3; ++i)
        u2[i] = E[i][0] * v2[0] + E[i][1] * v2[1] + E[i][2] * v2[2];
    {
        float d = u1[0]*u2[0] + u1[1]*u2[1] + u1[2]*u2[2];
        u2[0] -= d * u1[0]; u2[1] -= d * u1[1]; u2[2] -= d * u1[2];
        float nn = rsqrtf(u2[0]*u2[0] + u2[1]*u2[1] + u2[2]*u2[2]);
        u2[0] *= nn; u2[1] *= nn; u2[2] *= nn;
    }
    u3[0] = u1[1] * u2[2] - u1[2] * u2[1];
    u3[1] = u1[2] * u2[0] - u1[0] * u2[2];
    u3[2] = u1[0] * u2[1] - u1[1] * u2[0];

    float Ev3[3];
#pragma unroll
    for (int i = 0; i < 3; ++i)
        Ev3[i] = E[i][0] * v3[0] + E[i][1] * v3[1] + E[i][2] * v3[2];
    float s3p = u3[0]*Ev3[0] + u3[1]*Ev3[1] + u3[2]*Ev3[2];
    if (s3p < 0.f) { v3[0] = -v3[0]; v3[1] = -v3[1]; v3[2] = -v3[2]; }

    float R1[9], R2[9];
#pragma unroll
    for (int i = 0; i < 3; ++i)
#pragma unroll
        for (int j = 0; j < 3; ++j) {
            float c3 = u3[i] * v3[j];
            R1[3 * i + j] =  u2[i] * v1[j] - u1[i] * v2[j] + c3;
            R2[3 * i + j] = -u2[i] * v1[j] + u1[i] * v2[j] + c3;
        }
    float d1 = R1[0]*(R1[4]*R1[8]-R1[5]*R1[7]) - R1[1]*(R1[3]*R1[8]-R1[5]*R1[6]) + R1[2]*(R1[3]*R1[7]-R1[4]*R1[6]);
    float d2 = R2[0]*(R2[4]*R2[8]-R2[5]*R2[7]) - R2[1]*(R2[3]*R2[8]-R2[5]*R2[6]) + R2[2]*(R2[3]*R2[7]-R2[4]*R2[6]);
    float sg1 = (d1 < 0.f) ? -1.f : 1.f;
    float sg2 = (d2 < 0.f) ? -1.f : 1.f;
    float* cd = g_cand + b * 21;
#pragma unroll
    for (int m = 0; m < 9; ++m) { cd[m] = R1[m] * sg1; cd[9 + m] = R2[m] * sg2; }
    cd[18] = u3[0]; cd[19] = u3[1]; cd[20] = u3[2];
}

// ---------------------------------------------------------------------------
// Kernel C: partial cheirality scoring + fused last-block finalize
// ---------------------------------------------------------------------------
__device__ __forceinline__ void score_pt(
    const float* R1, const float* R2, const float* tv,
    const float* Ki0, const float* Ki1,
    float ux0, float uy0, float ux1, float uy1, float w, float* sc)
{
    float x0[3], x1[3];
    x0[0] = fmaf(Ki0[0], ux0, fmaf(Ki0[1], uy0, Ki0[2]));
    x0[1] = fmaf(Ki0[3], ux0, fmaf(Ki0[4], uy0, Ki0[5]));
    x0[2] = fmaf(Ki0[6], ux0, fmaf(Ki0[7], uy0, Ki0[8]));
    x1[0] = fmaf(Ki1[0], ux1, fmaf(Ki1[1], uy1, Ki1[2]));
    x1[1] = fmaf(Ki1[3], ux1, fmaf(Ki1[4], uy1, Ki1[5]));
    x1[2] = fmaf(Ki1[6], ux1, fmaf(Ki1[7], uy1, Ki1[8]));

    float bb = x1[0]*x1[0] + x1[1]*x1[1] + x1[2]*x1[2];
    float bt = x1[0]*tv[0] + x1[1]*tv[1] + x1[2]*tv[2];
    {
        float a0 = R1[0]*x0[0] + R1[1]*x0[1] + R1[2]*x0[2];
        float a1 = R1[3]*x0[0] + R1[4]*x0[1] + R1[5]*x0[2];
        float a2 = R1[6]*x0[0] + R1[7]*x0[1] + R1[8]*x0[2];
        float aa = a0*a0 + a1*a1 + a2*a2;
        float ab = a0*x1[0] + a1*x1[1] + a2*x1[2];
        float at = a0*tv[0] + a1*tv[1] + a2*tv[2];
        float n0v = -at * bb + ab * bt;
        float n1v =  aa * bt - ab * at;
        if (n0v > 0.f && n1v > 0.f) sc[0] += w;
        if (n0v < 0.f && n1v < 0.f) sc[1] += w;
    }
    {
        float a0 = R2[0]*x0[0] + R2[1]*x0[1] + R2[2]*x0[2];
        float a1 = R2[3]*x0[0] + R2[4]*x0[1] + R2[5]*x0[2];
        float a2 = R2[6]*x0[0] + R2[7]*x0[1] + R2[8]*x0[2];
        float aa = a0*a0 + a1*a1 + a2*a2;
        float ab = a0*x1[0] + a1*x1[1] + a2*x1[2];
        float at = a0*tv[0] + a1*tv[1] + a2*tv[2];
        float n0v = -at * bb + ab * bt;
        float n1v =  aa * bt - ab * at;
        if (n0v > 0.f && n1v > 0.f) sc[2] += w;
        if (n0v < 0.f && n1v < 0.f) sc[3] += w;
    }
}

__global__ __launch_bounds__(256) void k_score(
    const float* __restrict__ kpts0, const float* __restrict__ kpts1,
    const float* __restrict__ conf,  const float* __restrict__ tscale,
    const float* __restrict__ K, float* __restrict__ out, int N)
{
    int b = blockIdx.x;
    int s = blockIdx.y;
    int NS = (N + SEGS - 1) / SEGS;
    int n0 = s * NS;
    int n1 = min(N, n0 + NS);

    float Ki0[9], Ki1[9];
    inv3x3(K + (size_t)b * 18, Ki0);
    inv3x3(K + (size_t)b * 18 + 9, Ki1);

    const float* cd = g_cand + b * 21;
    float R1[9], R2[9], tv[3];
#pragma unroll
    for (int m = 0; m < 9; ++m) { R1[m] = cd[m]; R2[m] = cd[9 + m]; }
    tv[0] = cd[18]; tv[1] = cd[19]; tv[2] = cd[20];

    const float4* p0v = (const float4*)(kpts0 + (size_t)b * N * 2);
    const float4* p1v = (const float4*)(kpts1 + (size_t)b * N * 2);
    const float4* pwv = (const float4*)(conf  + (size_t)b * N);
    const float2* p0  = (const float2*)(kpts0 + (size_t)b * N * 2);
    const float2* p1  = (const float2*)(kpts1 + (size_t)b * N * 2);
    const float*  pw  = conf + (size_t)b * N;

    float sc[4] = {0.f, 0.f, 0.f, 0.f};
    int span = n1 - n0;
    int nvec = n0 + (span / 1024) * 1024;
    for (int base = n0 + threadIdx.x * 4; base + 4 <= nvec; base += 1024) {
        float4 a0[2], a1[2], wv;
        int h = base >> 1;
        a0[0] = p0v[h]; a0[1] = p0v[h + 1];
        a1[0] = p1v[h]; a1[1] = p1v[h + 1];
        wv = pwv[base >> 2];
        const float* wf = (const float*)&wv;
#pragma unroll
        for (int j = 0; j < 4; ++j) {
            float ux0 = (j & 1) ? a0[j >> 1].z : a0[j >> 1].x;
            float uy0 = (j & 1) ? a0[j >> 1].w : a0[j >> 1].y;
            float ux1 = (j & 1) ? a1[j >> 1].z : a1[j >> 1].x;
            float uy1 = (j & 1) ? a1[j >> 1].w : a1[j >> 1].y;
            score_pt(R1, R2, tv, Ki0, Ki1, ux0, uy0, ux1, uy1, wf[j], sc);
        }
    }
    for (int n = nvec + threadIdx.x; n < n1; n += 256) {
        float2 u0 = p0[n];
        float2 u1 = p1[n];
        score_pt(R1, R2, tv, Ki0, Ki1, u0.x, u0.y, u1.x, u1.y, pw[n], sc);
    }

    __shared__ float red[8][4];
    __shared__ bool amLast;
    int lane = threadIdx.x & 31, wid = threadIdx.x >> 5;
#pragma unroll
    for (int m = 0; m < 4; ++m) {
#pragma unroll
        for (int o = 16; o > 0; o >>= 1)
            sc[m] += __shfl_xor_sync(0xffffffffu, sc[m], o);
    }
    if (lane == 0) {
#pragma unroll
        for (int m = 0; m < 4; ++m) red[wid][m] = sc[m];
    }
    __syncthreads();

    if (threadIdx.x == 0) {
        float part[4];
        int nw = blockDim.x >> 5;
#pragma unroll
        for (int m = 0; m < 4; ++m) {
            float sum = 0.f;
            for (int wd = 0; wd < nw; ++wd) sum += red[wd][m];
            part[m] = sum;
        }
        float* dst = g_sc + ((size_t)b * SEGS + s) * 4;
#pragma unroll
        for (int m = 0; m < 4; ++m) dst[m] = part[m];
        __threadfence();
        int prev = atomicAdd(&g_cnt[b], 1);
        amLast = (prev == SEGS - 1);
    }
    __syncthreads();

    if (amLast && threadIdx.x == 0) {
        __threadfence();
        // deterministic fixed-order sum over segments
        float stot[4] = {0.f, 0.f, 0.f, 0.f};
        for (int seg = 0; seg < SEGS; ++seg) {
            const float* p = g_sc + ((size_t)b * SEGS + seg) * 4;
#pragma unroll
            for (int m = 0; m < 4; ++m) stot[m] += p[m];
        }
        int best = 0;
        for (int c = 1; c < 4; ++c) if (stot[c] > stot[best]) best = c;

        float R[9];
        const float* Rs = (best < 2) ? R1 : R2;
#pragma unroll
        for (int m = 0; m < 9; ++m) R[m] = Rs[m];
        float sg = (best & 1) ? -1.f : 1.f;
        float ts = tscale[(size_t)b * 2];
        float t0 = sg * tv[0] * ts, t1 = sg * tv[1] * ts, t2 = sg * tv[2] * ts;

        float* o01 = out + (size_t)b * 32;
        float* o10 = o01 + 16;
        o01[0]  = R[0]; o01[1]  = R[1]; o01[2]  = R[2]; o01[3]  = t0;
        o01[4]  = R[3]; o01[5]  = R[4]; o01[6]  = R[5]; o01[7]  = t1;
        o01[8]  = R[6]; o01[9]  = R[7]; o01[10] = R[8]; o01[11] = t2;
        o01[12] = 0.f;  o01[13] = 0.f;  o01[14] = 0.f;  o01[15] = 1.f;
        float ti0 = -(R[0] * t0 + R[3] * t1 + R[6] * t2);
        float ti1 = -(R[1] * t0 + R[4] * t1 + R[7] * t2);
        float ti2 = -(R[2] * t0 + R[5] * t1 + R[8] * t2);
        o10[0]  = R[0]; o10[1]  = R[3]; o10[2]  = R[6]; o10[3]  = ti0;
        o10[4]  = R[1]; o10[5]  = R[4]; o10[6]  = R[7]; o10[7]  = ti1;
        o10[8]  = R[2]; o10[9]  = R[5]; o10[10] = R[8]; o10[11] = ti2;
        o10[12] = 0.f;  o10[13] = 0.f;  o10[14] = 0.f;  o10[15] = 1.f;

        g_cnt[b] = 0;   // reset for next graph replay
    }
}

// ---------------------------------------------------------------------------
extern "C" void kernel_launch(void* const* d_in, const int* in_sizes, int n_in,
                              void* d_out, int out_size)
{
    const float* kpts0 = (const float*)d_in[0];
    const float* kpts1 = (const float*)d_in[1];
    const float* conf  = (const float*)d_in[2];
    const float* tsc   = (const float*)d_in[3];
    const float* K     = (const float*)d_in[4];

    int B = in_sizes[4] / 18;        // K: (B, 2, 3, 3)
    int N = in_sizes[2] / B;         // conf: (B, N, 1)

    dim3 gridA(B, SEGA);
    k_accumM<<<gridA, 256>>>(kpts0, kpts1, conf, K, N);
    k_solve<<<(B + 63) / 64, 64>>>(B);
    dim3 gridC(B, SEGS);
    k_score<<<gridC, 256>>>(kpts0, kpts1, conf, tsc, K, (float*)d_out, N);
}

// round 12
// speedup vs baseline: 2.4140x; 1.2760x over previous
#include <cuda_runtime.h>
#include <math.h>

#define MAXB 2048
#define SEGS 2

// scratch (no allocations allowed)
__device__ float g_cand[MAXB * 21];       // R1(9), R2(9), t(3)
__device__ float g_sc[MAXB * SEGS * 4];   // per-(batch,seg) candidate scores
__device__ int   g_cnt[MAXB];             // per-batch done-counter (self-resetting)

// fixed affine preconditioner: x' = u/320 - 1, y' = v/240 - 1
#define PSX (1.0f / 320.0f)
#define PSY (1.0f / 240.0f)

// upper-tri index (i <= j), 9x9 -> 45
#define SU(i, j) ((i) * 9 - (i) * ((i) + 1) / 2 + (j))
// lower-tri index (j <= i)
#define LT(i, j) ((i) * ((i) + 1) / 2 + (j))
// symmetric access of ms[45]
#define ASYM(ms, i, j) ((i) <= (j) ? (ms)[SU(i, j)] : (ms)[SU(j, i)])
// 3x3 symmetric pair index (i <= k)
#define S3(i, k) ((i) * (5 - (i)) / 2 + (k))

__device__ __forceinline__ void inv3x3(const float* __restrict__ K, float* Ki) {
    float a = K[0], b = K[1], c = K[2];
    float d = K[3], e = K[4], f = K[5];
    float g = K[6], h = K[7], i = K[8];
    float A =  (e * i - f * h);
    float Bc = -(d * i - f * g);
    float C =  (d * h - e * g);
    float det = a * A + b * Bc + c * C;
    float id = 1.0f / det;
    Ki[0] = A * id;             Ki[1] = (c * h - b * i) * id; Ki[2] = (b * f - c * e) * id;
    Ki[3] = Bc * id;            Ki[4] = (a * i - c * g) * id; Ki[5] = (c * d - a * f) * id;
    Ki[6] = C * id;             Ki[7] = (b * g - a * h) * id; Ki[8] = (a * e - b * d) * id;
}

// N = Kinv * S^-1, where S^-1 = [[320,0,320],[0,240,240],[0,0,1]]
__device__ __forceinline__ void make_N(const float* Ki, float* Nm) {
#pragma unroll
    for (int r = 0; r < 3; ++r) {
        Nm[r * 3 + 0] = Ki[r * 3 + 0] * 320.f;
        Nm[r * 3 + 1] = Ki[r * 3 + 1] * 240.f;
        Nm[r * 3 + 2] = Ki[r * 3 + 0] * 320.f + Ki[r * 3 + 1] * 240.f + Ki[r * 3 + 2];
    }
}

__device__ __forceinline__ void chol9(const float* __restrict__ ms, float shift,
                                      float* __restrict__ L, float* __restrict__ invd)
{
#pragma unroll
    for (int k = 0; k < 9; ++k) {
        float sdiag = ms[SU(k, k)] - shift;
#pragma unroll
        for (int j = 0; j < k; ++j) sdiag -= L[LT(k, j)] * L[LT(k, j)];
        float d = sqrtf(fmaxf(sdiag, 1e-25f));
        L[LT(k, k)] = d;
        float inv = 1.f / d;
        invd[k] = inv;
#pragma unroll
        for (int i = k + 1; i < 9; ++i) {
            float t = ASYM(ms, i, k);
#pragma unroll
            for (int j = 0; j < k; ++j) t -= L[LT(i, j)] * L[LT(k, j)];
            L[LT(i, k)] = t * inv;
        }
    }
}

__device__ __forceinline__ void cholsolve9(const float* __restrict__ L,
                                           const float* __restrict__ invd,
                                           const float* __restrict__ x,
                                           float* __restrict__ z)
{
    float y[9];
#pragma unroll
    for (int i = 0; i < 9; ++i) {
        float t = x[i];
#pragma unroll
        for (int j = 0; j < i; ++j) t -= L[LT(i, j)] * y[j];
        y[i] = t * invd[i];
    }
#pragma unroll
    for (int i = 8; i >= 0; --i) {
        float t = y[i];
#pragma unroll
        for (int j = i + 1; j < 9; ++j) t -= L[LT(j, i)] * z[j];
        z[i] = t * invd[i];
    }
}

// full solve from raw moments Tsm[36] -> writes g_cand[b]
__device__ void solve_from_T(const float* __restrict__ Tsm, const float* __restrict__ K,
                             int b)
{
    float Ki0[9], Ki1[9], N0[9], N1[9];
    inv3x3(K + (size_t)b * 18, Ki0);
    inv3x3(K + (size_t)b * 18 + 9, Ki1);
    make_N(Ki0, N0);
    make_N(Ki1, N1);

    // C rows: C_a = N0 * R_a * N0^T (R_a symmetric from T row a)
    float C[36];
#pragma unroll
    for (int a = 0; a < 6; ++a) {
        float r00 = Tsm[a * 6 + 0], r01 = Tsm[a * 6 + 1], r02 = Tsm[a * 6 + 2];
        float r11 = Tsm[a * 6 + 3], r12 = Tsm[a * 6 + 4], r22 = Tsm[a * 6 + 5];
        float U[3][3];
#pragma unroll
        for (int r = 0; r < 3; ++r) {
            U[r][0] = N0[r * 3 + 0] * r00 + N0[r * 3 + 1] * r01 + N0[r * 3 + 2] * r02;
            U[r][1] = N0[r * 3 + 0] * r01 + N0[r * 3 + 1] * r11 + N0[r * 3 + 2] * r12;
            U[r][2] = N0[r * 3 + 0] * r02 + N0[r * 3 + 1] * r12 + N0[r * 3 + 2] * r22;
        }
#pragma unroll
        for (int r = 0; r < 3; ++r)
#pragma unroll
            for (int c = r; c < 3; ++c)
                C[a * 6 + S3(r, c)] =
                    U[r][0] * N0[c * 3 + 0] + U[r][1] * N0[c * 3 + 1] + U[r][2] * N0[c * 3 + 2];
    }

    // M blocks: M[blk(i',k')] = sum over (i,k) pairs of coef * C_pair ; blocks symmetric
    float ms[45];
#pragma unroll
    for (int ip = 0; ip < 3; ++ip) {
#pragma unroll
        for (int kp = 0; kp < 3; ++kp) {
            if (kp < ip) continue;
            float wc[6];
            wc[S3(0, 0)] = N1[ip * 3 + 0] * N1[kp * 3 + 0];
            wc[S3(1, 1)] = N1[ip * 3 + 1] * N1[kp * 3 + 1];
            wc[S3(2, 2)] = N1[ip * 3 + 2] * N1[kp * 3 + 2];
            wc[S3(0, 1)] = N1[ip * 3 + 0] * N1[kp * 3 + 1] + N1[ip * 3 + 1] * N1[kp * 3 + 0];
            wc[S3(0, 2)] = N1[ip * 3 + 0] * N1[kp * 3 + 2] + N1[ip * 3 + 2] * N1[kp * 3 + 0];
            wc[S3(1, 2)] = N1[ip * 3 + 1] * N1[kp * 3 + 2] + N1[ip * 3 + 2] * N1[kp * 3 + 1];
            float D[6];
#pragma unroll
            for (int q = 0; q < 6; ++q) {
                float s = 0.f;
#pragma unroll
                for (int p = 0; p < 6; ++p) s += wc[p] * C[p * 6 + q];
                D[q] = s;
            }
#pragma unroll
            for (int jp = 0; jp < 3; ++jp)
#pragma unroll
                for (int lp = 0; lp < 3; ++lp) {
                    int r = 3 * ip + jp, c = 3 * kp + lp;
                    if (c < r) continue;
                    int jj = (jp < lp) ? jp : lp;
                    int ll = (jp < lp) ? lp : jp;
                    ms[SU(r, c)] = D[S3(jj, ll)];
                }
        }
    }

    float tr = 0.f;
#pragma unroll
    for (int k = 0; k < 9; ++k) tr += ms[SU(k, k)];
    float eps = 1e-7f * tr;
#pragma unroll
    for (int k = 0; k < 9; ++k) ms[SU(k, k)] += eps;

    float L[45], invd[9];
    chol9(ms, 0.f, L, invd);

    float v[9];
#pragma unroll
    for (int i = 0; i < 9; ++i) v[i] = 1.f / 3.f;

    float z[9];
#pragma unroll
    for (int it = 0; it < 8; ++it) {   // 8 steps: proven sufficient
        cholsolve9(L, invd, v, z);
        float nn = 0.f;
#pragma unroll
        for (int i = 0; i < 9; ++i) nn += z[i] * z[i];
        float inv = rsqrtf(nn);
#pragma unroll
        for (int i = 0; i < 9; ++i) v[i] = z[i] * inv;
    }
    float rho = 0.f;
#pragma unroll
    for (int i = 0; i < 9; ++i) {
        float t = 0.f;
#pragma unroll
        for (int j = 0; j < 9; ++j) t += ASYM(ms, i, j) * v[j];
        rho += v[i] * t;
    }
    chol9(ms, 0.95f * rho, L, invd);
#pragma unroll
    for (int it = 0; it < 3; ++it) {
        cholsolve9(L, invd, v, z);
        float nn = 0.f;
#pragma unroll
        for (int i = 0; i < 9; ++i) nn += z[i] * z[i];
        float inv = rsqrtf(nn);
#pragma unroll
        for (int i = 0; i < 9; ++i) v[i] = z[i] * inv;
    }

    float E[3][3];
#pragma unroll
    for (int i = 0; i < 3; ++i)
#pragma unroll
        for (int j = 0; j < 3; ++j) E[i][j] = v[3 * i + j];

    float G[3][3];
#pragma unroll
    for (int i = 0; i < 3; ++i)
#pragma unroll
        for (int j = 0; j < 3; ++j) {
            float s = 0.f;
#pragma unroll
            for (int k = 0; k < 3; ++k) s += E[k][i] * E[k][j];
            G[i][j] = s;
        }
    float ev[3][3] = {{1.f,0.f,0.f},{0.f,1.f,0.f},{0.f,0.f,1.f}};

#define J3(P, Q, R) do {                                                      \
    float app = G[P][P], aqq = G[Q][Q], apq = G[P][Q];                        \
    if (fabsf(apq) > 1e-14f * (fabsf(app) + fabsf(aqq))) {                    \
        float tau = (aqq - app) / (2.f * apq);                                \
        float tt  = copysignf(1.f, tau) / (fabsf(tau) + sqrtf(1.f + tau * tau)); \
        float c   = 1.f / sqrtf(1.f + tt * tt);                               \
        float s   = tt * c;                                                   \
        float apr = G[P][R], aqr = G[Q][R];                                   \
        G[P][P] = app - tt * apq; G[Q][Q] = aqq + tt * apq;                   \
        G[P][Q] = 0.f; G[Q][P] = 0.f;                                         \
        G[P][R] = c * apr - s * aqr; G[R][P] = G[P][R];                       \
        G[Q][R] = s * apr + c * aqr; G[R][Q] = G[Q][R];                       \
        for (int kk = 0; kk < 3; ++kk) {                                      \
            float vp = ev[kk][P], vq = ev[kk][Q];                             \
            ev[kk][P] = c * vp - s * vq;                                      \
            ev[kk][Q] = s * vp + c * vq;                                      \
        }                                                                     \
    } } while (0)

#pragma unroll
    for (int sw = 0; sw < 8; ++sw) { J3(0, 1, 2); J3(0, 2, 1); J3(1, 2, 0); }
#undef J3

    float l0 = G[0][0], l1 = G[1][1], l2 = G[2][2];
    int i0 = 0, i1 = 1, i2 = 2;
    if (l1 > l0) { float tm = l0; l0 = l1; l1 = tm; int ti = i0; i0 = i1; i1 = ti; }
    if (l2 > l0) { float tm = l0; l0 = l2; l2 = tm; int ti = i0; i0 = i2; i2 = ti; }
    if (l2 > l1) { float tm = l1; l1 = l2; l2 = tm; int ti = i1; i1 = i2; i2 = ti; }

    float v1[3], v2[3], v3[3];
#pragma unroll
    for (int k = 0; k < 3; ++k) { v1[k] = ev[k][i0]; v2[k] = ev[k][i1]; v3[k] = ev[k][i2]; }

    float u1[3], u2[3], u3[3];
#pragma unroll
    for (int i = 0; i < 3; ++i)
        u1[i] = E[i][0] * v1[0] + E[i][1] * v1[1] + E[i][2] * v1[2];
    {
        float nn = rsqrtf(u1[0]*u1[0] + u1[1]*u1[1] + u1[2]*u1[2]);
        u1[0] *= nn; u1[1] *= nn; u1[2] *= nn;
    }
#pragma unroll
    for (int i = 0; i < 3; ++i)
        u2[i] = E[i][0] * v2[0] + E[i][1] * v2[1] + E[i][2] * v2[2];
    {
        float d = u1[0]*u2[0] + u1[1]*u2[1] + u1[2]*u2[2];
        u2[0] -= d * u1[0]; u2[1] -= d * u1[1]; u2[2] -= d * u1[2];
        float nn = rsqrtf(u2[0]*u2[0] + u2[1]*u2[1] + u2[2]*u2[2]);
        u2[0] *= nn; u2[1] *= nn; u2[2] *= nn;
    }
    u3[0] = u1[1] * u2[2] - u1[2] * u2[1];
    u3[1] = u1[2] * u2[0] - u1[0] * u2[2];
    u3[2] = u1[0] * u2[1] - u1[1] * u2[0];

    float Ev3[3];
#pragma unroll
    for (int i = 0; i < 3; ++i)
        Ev3[i] = E[i][0] * v3[0] + E[i][1] * v3[1] + E[i][2] * v3[2];
    float s3p = u3[0]*Ev3[0] + u3[1]*Ev3[1] + u3[2]*Ev3[2];
    if (s3p < 0.f) { v3[0] = -v3[0]; v3[1] = -v3[1]; v3[2] = -v3[2]; }

    float R1[9], R2[9];
#pragma unroll
    for (int i = 0; i < 3; ++i)
#pragma unroll
        for (int j = 0; j < 3; ++j) {
            float c3 = u3[i] * v3[j];
            R1[3 * i + j] =  u2[i] * v1[j] - u1[i] * v2[j] + c3;
            R2[3 * i + j] = -u2[i] * v1[j] + u1[i] * v2[j] + c3;
        }
    float d1 = R1[0]*(R1[4]*R1[8]-R1[5]*R1[7]) - R1[1]*(R1[3]*R1[8]-R1[5]*R1[6]) + R1[2]*(R1[3]*R1[7]-R1[4]*R1[6]);
    float d2 = R2[0]*(R2[4]*R2[8]-R2[5]*R2[7]) - R2[1]*(R2[3]*R2[8]-R2[5]*R2[6]) + R2[2]*(R2[3]*R2[7]-R2[4]*R2[6]);
    float sg1 = (d1 < 0.f) ? -1.f : 1.f;
    float sg2 = (d2 < 0.f) ? -1.f : 1.f;
    float* cd = g_cand + b * 21;
#pragma unroll
    for (int m = 0; m < 9; ++m) { cd[m] = R1[m] * sg1; cd[9 + m] = R2[m] * sg2; }
    cd[18] = u3[0]; cd[19] = u3[1]; cd[20] = u3[2];
}

// ---------------------------------------------------------------------------
// Kernel 1: fused raw-moment accumulation (preconditioned coords) + solve
// One block per batch. Thread 0 finishes with the eigen/SVD solve.
// ---------------------------------------------------------------------------
__global__ void __launch_bounds__(256, 2) k_accum_solve(
    const float* __restrict__ kpts0, const float* __restrict__ kpts1,
    const float* __restrict__ conf,  const float* __restrict__ K, int N)
{
    int b = blockIdx.x;

    float acc[36];
#pragma unroll
    for (int m = 0; m < 36; ++m) acc[m] = 0.f;

    const float4* p0v = (const float4*)(kpts0 + (size_t)b * N * 2);
    const float4* p1v = (const float4*)(kpts1 + (size_t)b * N * 2);
    const float4* pwv = (const float4*)(conf  + (size_t)b * N);
    const float2* p0  = (const float2*)(kpts0 + (size_t)b * N * 2);
    const float2* p1  = (const float2*)(kpts1 + (size_t)b * N * 2);
    const float*  pw  = conf + (size_t)b * N;

    auto do_pt = [&](float ux0, float uy0, float ux1, float uy1, float w) {
        float x0p = fmaf(ux0, PSX, -1.f);
        float y0p = fmaf(uy0, PSY, -1.f);
        float x1p = fmaf(ux1, PSX, -1.f);
        float y1p = fmaf(uy1, PSY, -1.f);
        float P[6], Q[6];
        P[0] = x1p * x1p; P[1] = x1p * y1p; P[2] = x1p;
        P[3] = y1p * y1p; P[4] = y1p;      P[5] = 1.f;
        Q[0] = x0p * x0p; Q[1] = x0p * y0p; Q[2] = x0p;
        Q[3] = y0p * y0p; Q[4] = y0p;      Q[5] = 1.f;
#pragma unroll
        for (int a = 0; a < 6; ++a) {
            float t = w * P[a];
#pragma unroll
            for (int q = 0; q < 6; ++q)
                acc[a * 6 + q] = fmaf(t, Q[q], acc[a * 6 + q]);
        }
    };

    if (N == 4096) {
        // each thread owns 16 contiguous points; 2 batches of 8 with front-loaded MLP
        int base = threadIdx.x * 16;
#pragma unroll
        for (int h = 0; h < 2; ++h) {
            int nb = base + h * 8;
            float4 a0[4], a1[4], wv[2];
            int q4 = nb >> 1;
#pragma unroll
            for (int k = 0; k < 4; ++k) { a0[k] = p0v[q4 + k]; a1[k] = p1v[q4 + k]; }
            wv[0] = pwv[nb >> 2];
            wv[1] = pwv[(nb >> 2) + 1];
            const float* wf = (const float*)wv;
#pragma unroll
            for (int j = 0; j < 8; ++j) {
                float ux0 = (j & 1) ? a0[j >> 1].z : a0[j >> 1].x;
                float uy0 = (j & 1) ? a0[j >> 1].w : a0[j >> 1].y;
                float ux1 = (j & 1) ? a1[j >> 1].z : a1[j >> 1].x;
                float uy1 = (j & 1) ? a1[j >> 1].w : a1[j >> 1].y;
                do_pt(ux0, uy0, ux1, uy1, wf[j]);
            }
        }
    } else {
        for (int n = threadIdx.x; n < N; n += 256) {
            float2 u0 = p0[n];
            float2 u1 = p1[n];
            do_pt(u0.x, u0.y, u1.x, u1.y, pw[n]);
        }
    }

    // block reduction of 36 values into shared T
    __shared__ float red[8][36];
    __shared__ float Tsm[36];
    int lane = threadIdx.x & 31, wid = threadIdx.x >> 5;
#pragma unroll
    for (int m = 0; m < 36; ++m) {
#pragma unroll
        for (int o = 16; o > 0; o >>= 1)
            acc[m] += __shfl_xor_sync(0xffffffffu, acc[m], o);
    }
    if (lane == 0) {
#pragma unroll
        for (int m = 0; m < 36; ++m) red[wid][m] = acc[m];
    }
    __syncthreads();
    if (threadIdx.x < 36) {
        float sum = 0.f;
#pragma unroll
        for (int wd = 0; wd < 8; ++wd) sum += red[wd][threadIdx.x];
        Tsm[threadIdx.x] = sum;
    }
    __syncthreads();

    if (threadIdx.x == 0)
        solve_from_T(Tsm, K, b);
}

// ---------------------------------------------------------------------------
// Kernel 2: cheirality scoring with fused matrices + last-block finalize
// ---------------------------------------------------------------------------
__global__ void __launch_bounds__(256) k_score(
    const float* __restrict__ kpts0, const float* __restrict__ kpts1,
    const float* __restrict__ conf,  const float* __restrict__ tscale,
    const float* __restrict__ K, float* __restrict__ out, int N)
{
    int b = blockIdx.x;
    int s = blockIdx.y;

    float Ki0[9], Ki1[9], N0[9], N1[9];
    inv3x3(K + (size_t)b * 18, Ki0);
    inv3x3(K + (size_t)b * 18 + 9, Ki1);
    make_N(Ki0, N0);
    make_N(Ki1, N1);

    const float* cd = g_cand + b * 21;
    float tv[3] = {cd[18], cd[19], cd[20]};
    // fused: A1 = R1*N0, A2 = R2*N0 (apply directly to preconditioned homog coords)
    float A1[9], A2[9];
#pragma unroll
    for (int r = 0; r < 3; ++r)
#pragma unroll
        for (int c = 0; c < 3; ++c) {
            float s1 = 0.f, s2 = 0.f;
#pragma unroll
            for (int k = 0; k < 3; ++k) {
                s1 += cd[r * 3 + k] * N0[k * 3 + c];
                s2 += cd[9 + r * 3 + k] * N0[k * 3 + c];
            }
            A1[r * 3 + c] = s1;
            A2[r * 3 + c] = s2;
        }

    const float4* p0v = (const float4*)(kpts0 + (size_t)b * N * 2);
    const float4* p1v = (const float4*)(kpts1 + (size_t)b * N * 2);
    const float4* pwv = (const float4*)(conf  + (size_t)b * N);
    const float2* p0  = (const float2*)(kpts0 + (size_t)b * N * 2);
    const float2* p1  = (const float2*)(kpts1 + (size_t)b * N * 2);
    const float*  pw  = conf + (size_t)b * N;

    float sc[4] = {0.f, 0.f, 0.f, 0.f};

    auto do_pt = [&](float ux0, float uy0, float ux1, float uy1, float w) {
        float x0p = fmaf(ux0, PSX, -1.f);
        float y0p = fmaf(uy0, PSY, -1.f);
        float x1p = fmaf(ux1, PSX, -1.f);
        float y1p = fmaf(uy1, PSY, -1.f);
        float b0 = fmaf(N1[0], x1p, fmaf(N1[1], y1p, N1[2]));
        float b1 = fmaf(N1[3], x1p, fmaf(N1[4], y1p, N1[5]));
        float b2 = fmaf(N1[6], x1p, fmaf(N1[7], y1p, N1[8]));
        float bb = b0 * b0 + b1 * b1 + b2 * b2;
        float bt = b0 * tv[0] + b1 * tv[1] + b2 * tv[2];
        {
            float a0 = fmaf(A1[0], x0p, fmaf(A1[1], y0p, A1[2]));
            float a1 = fmaf(A1[3], x0p, fmaf(A1[4], y0p, A1[5]));
            float a2 = fmaf(A1[6], x0p, fmaf(A1[7], y0p, A1[8]));
            float aa = a0 * a0 + a1 * a1 + a2 * a2;
            float ab = a0 * b0 + a1 * b1 + a2 * b2;
            float at = a0 * tv[0] + a1 * tv[1] + a2 * tv[2];
            float n0v = ab * bt - at * bb;
            float n1v = aa * bt - ab * at;
            if (n0v > 0.f && n1v > 0.f) sc[0] += w;
            if (n0v < 0.f && n1v < 0.f) sc[1] += w;
        }
        {
            float a0 = fmaf(A2[0], x0p, fmaf(A2[1], y0p, A2[2]));
            float a1 = fmaf(A2[3], x0p, fmaf(A2[4], y0p, A2[5]));
            float a2 = fmaf(A2[6], x0p, fmaf(A2[7], y0p, A2[8]));
            float aa = a0 * a0 + a1 * a1 + a2 * a2;
            float ab = a0 * b0 + a1 * b1 + a2 * b2;
            float at = a0 * tv[0] + a1 * tv[1] + a2 * tv[2];
            float n0v = ab * bt - at * bb;
            float n1v = aa * bt - ab * at;
            if (n0v > 0.f && n1v > 0.f) sc[2] += w;
            if (n0v < 0.f && n1v < 0.f) sc[3] += w;
        }
    };

    if (N == 4096) {
        int base = s * 2048 + threadIdx.x * 8;   // 8 contiguous pts per thread
        float4 a0[4], a1[4], wv[2];
        int q4 = base >> 1;
#pragma unroll
        for (int k = 0; k < 4; ++k) { a0[k] = p0v[q4 + k]; a1[k] = p1v[q4 + k]; }
        wv[0] = pwv[base >> 2];
        wv[1] = pwv[(base >> 2) + 1];
        const float* wf = (const float*)wv;
#pragma unroll
        for (int j = 0; j < 8; ++j) {
            float ux0 = (j & 1) ? a0[j >> 1].z : a0[j >> 1].x;
            float uy0 = (j & 1) ? a0[j >> 1].w : a0[j >> 1].y;
            float ux1 = (j & 1) ? a1[j >> 1].z : a1[j >> 1].x;
            float uy1 = (j & 1) ? a1[j >> 1].w : a1[j >> 1].y;
            do_pt(ux0, uy0, ux1, uy1, wf[j]);
        }
    } else {
        int NS = (N + SEGS - 1) / SEGS;
        int n0i = s * NS;
        int n1i = min(N, n0i + NS);
        for (int n = n0i + threadIdx.x; n < n1i; n += 256) {
            float2 u0 = p0[n];
            float2 u1 = p1[n];
            do_pt(u0.x, u0.y, u1.x, u1.y, pw[n]);
        }
    }

    __shared__ float red[8][4];
    __shared__ bool amLast;
    int lane = threadIdx.x & 31, wid = threadIdx.x >> 5;
#pragma unroll
    for (int m = 0; m < 4; ++m) {
#pragma unroll
        for (int o = 16; o > 0; o >>= 1)
            sc[m] += __shfl_xor_sync(0xffffffffu, sc[m], o);
    }
    if (lane == 0) {
#pragma unroll
        for (int m = 0; m < 4; ++m) red[wid][m] = sc[m];
    }
    __syncthreads();

    if (threadIdx.x == 0) {
        float part[4];
#pragma unroll
        for (int m = 0; m < 4; ++m) {
            float sum = 0.f;
#pragma unroll
            for (int wd = 0; wd < 8; ++wd) sum += red[wd][m];
            part[m] = sum;
        }
        float* dst = g_sc + ((size_t)b * SEGS + s) * 4;
#pragma unroll
        for (int m = 0; m < 4; ++m) dst[m] = part[m];
        __threadfence();
        int prev = atomicAdd(&g_cnt[b], 1);
        amLast = (prev == SEGS - 1);
    }
    __syncthreads();

    if (amLast && threadIdx.x == 0) {
        __threadfence();
        float stot[4] = {0.f, 0.f, 0.f, 0.f};
        for (int seg = 0; seg < SEGS; ++seg) {
            const float* p = g_sc + ((size_t)b * SEGS + seg) * 4;
#pragma unroll
            for (int m = 0; m < 4; ++m) stot[m] += p[m];
        }
        int best = 0;
        for (int c = 1; c < 4; ++c) if (stot[c] > stot[best]) best = c;

        float R[9];
        const float* Rs = (best < 2) ? cd : cd + 9;
#pragma unroll
        for (int m = 0; m < 9; ++m) R[m] = Rs[m];
        float sg = (best & 1) ? -1.f : 1.f;
        float ts = tscale[(size_t)b * 2];
        float t0 = sg * tv[0] * ts, t1 = sg * tv[1] * ts, t2 = sg * tv[2] * ts;

        float* o01 = out + (size_t)b * 32;
        float* o10 = o01 + 16;
        o01[0]  = R[0]; o01[1]  = R[1]; o01[2]  = R[2]; o01[3]  = t0;
        o01[4]  = R[3]; o01[5]  = R[4]; o01[6]  = R[5]; o01[7]  = t1;
        o01[8]  = R[6]; o01[9]  = R[7]; o01[10] = R[8]; o01[11] = t2;
        o01[12] = 0.f;  o01[13] = 0.f;  o01[14] = 0.f;  o01[15] = 1.f;
        float ti0 = -(R[0] * t0 + R[3] * t1 + R[6] * t2);
        float ti1 = -(R[1] * t0 + R[4] * t1 + R[7] * t2);
        float ti2 = -(R[2] * t0 + R[5] * t1 + R[8] * t2);
        o10[0]  = R[0]; o10[1]  = R[3]; o10[2]  = R[6]; o10[3]  = ti0;
        o10[4]  = R[1]; o10[5]  = R[4]; o10[6]  = R[7]; o10[7]  = ti1;
        o10[8]  = R[2]; o10[9]  = R[5]; o10[10] = R[8]; o10[11] = ti2;
        o10[12] = 0.f;  o10[13] = 0.f;  o10[14] = 0.f;  o10[15] = 1.f;

        g_cnt[b] = 0;   // reset for next graph replay
    }
}

// ---------------------------------------------------------------------------
extern "C" void kernel_launch(void* const* d_in, const int* in_sizes, int n_in,
                              void* d_out, int out_size)
{
    const float* kpts0 = (const float*)d_in[0];
    const float* kpts1 = (const float*)d_in[1];
    const float* conf  = (const float*)d_in[2];
    const float* tsc   = (const float*)d_in[3];
    const float* K     = (const float*)d_in[4];

    int B = in_sizes[4] / 18;        // K: (B, 2, 3, 3)
    int N = in_sizes[2] / B;         // conf: (B, N, 1)

    k_accum_solve<<<B, 256>>>(kpts0, kpts1, conf, K, N);
    dim3 gridC(B, SEGS);
    k_score<<<gridC, 256>>>(kpts0, kpts1, conf, tsc, K, (float*)d_out, N);
}

// round 13
// speedup vs baseline: 2.6667x; 1.1047x over previous
#include <cuda_runtime.h>
#include <math.h>

// fixed affine preconditioner: x' = u/320 - 1, y' = v/240 - 1
#define PSX (1.0f / 320.0f)
#define PSY (1.0f / 240.0f)

// upper-tri index (i <= j), 9x9 -> 45
#define SU(i, j) ((i) * 9 - (i) * ((i) + 1) / 2 + (j))
// lower-tri index (j <= i)
#define LT(i, j) ((i) * ((i) + 1) / 2 + (j))
// symmetric access of ms[45]
#define ASYM(ms, i, j) ((i) <= (j) ? (ms)[SU(i, j)] : (ms)[SU(j, i)])
// 3x3 symmetric pair index (i <= k)
#define S3(i, k) ((i) * (5 - (i)) / 2 + (k))

__device__ __forceinline__ void inv3x3(const float* __restrict__ K, float* Ki) {
    float a = K[0], b = K[1], c = K[2];
    float d = K[3], e = K[4], f = K[5];
    float g = K[6], h = K[7], i = K[8];
    float A =  (e * i - f * h);
    float Bc = -(d * i - f * g);
    float C =  (d * h - e * g);
    float det = a * A + b * Bc + c * C;
    float id = 1.0f / det;
    Ki[0] = A * id;             Ki[1] = (c * h - b * i) * id; Ki[2] = (b * f - c * e) * id;
    Ki[3] = Bc * id;            Ki[4] = (a * i - c * g) * id; Ki[5] = (c * d - a * f) * id;
    Ki[6] = C * id;             Ki[7] = (b * g - a * h) * id; Ki[8] = (a * e - b * d) * id;
}

// N = Kinv * S^-1, where S^-1 = [[320,0,320],[0,240,240],[0,0,1]]
__device__ __forceinline__ void make_N(const float* Ki, float* Nm) {
#pragma unroll
    for (int r = 0; r < 3; ++r) {
        Nm[r * 3 + 0] = Ki[r * 3 + 0] * 320.f;
        Nm[r * 3 + 1] = Ki[r * 3 + 1] * 240.f;
        Nm[r * 3 + 2] = Ki[r * 3 + 0] * 320.f + Ki[r * 3 + 1] * 240.f + Ki[r * 3 + 2];
    }
}

__device__ __forceinline__ void chol9(const float* __restrict__ ms, float shift,
                                      float* __restrict__ L, float* __restrict__ invd)
{
#pragma unroll
    for (int k = 0; k < 9; ++k) {
        float sdiag = ms[SU(k, k)] - shift;
#pragma unroll
        for (int j = 0; j < k; ++j) sdiag -= L[LT(k, j)] * L[LT(k, j)];
        float d = sqrtf(fmaxf(sdiag, 1e-25f));
        L[LT(k, k)] = d;
        float inv = 1.f / d;
        invd[k] = inv;
#pragma unroll
        for (int i = k + 1; i < 9; ++i) {
            float t = ASYM(ms, i, k);
#pragma unroll
            for (int j = 0; j < k; ++j) t -= L[LT(i, j)] * L[LT(k, j)];
            L[LT(i, k)] = t * inv;
        }
    }
}

__device__ __forceinline__ void cholsolve9(const float* __restrict__ L,
                                           const float* __restrict__ invd,
                                           const float* __restrict__ x,
                                           float* __restrict__ z)
{
    float y[9];
#pragma unroll
    for (int i = 0; i < 9; ++i) {
        float t = x[i];
#pragma unroll
        for (int j = 0; j < i; ++j) t -= L[LT(i, j)] * y[j];
        y[i] = t * invd[i];
    }
#pragma unroll
    for (int i = 8; i >= 0; --i) {
        float t = y[i];
#pragma unroll
        for (int j = i + 1; j < 9; ++j) t -= L[LT(j, i)] * z[j];
        z[i] = t * invd[i];
    }
}

// full solve from raw moments Tsm[36].
// out48: [0..8]=R1s, [9..17]=R2s, [18..20]=t, [21..29]=A1=R1s*N0,
//        [30..38]=A2=R2s*N0, [39..47]=N1
__device__ void solve_from_T(const float* __restrict__ Tsm, const float* __restrict__ K,
                             int b, float* __restrict__ out48)
{
    float Ki0[9], Ki1[9], N0[9], N1[9];
    inv3x3(K + (size_t)b * 18, Ki0);
    inv3x3(K + (size_t)b * 18 + 9, Ki1);
    make_N(Ki0, N0);
    make_N(Ki1, N1);

    // C rows: C_a = N0 * R_a * N0^T (R_a symmetric from T row a)
    float C[36];
#pragma unroll
    for (int a = 0; a < 6; ++a) {
        float r00 = Tsm[a * 6 + 0], r01 = Tsm[a * 6 + 1], r02 = Tsm[a * 6 + 2];
        float r11 = Tsm[a * 6 + 3], r12 = Tsm[a * 6 + 4], r22 = Tsm[a * 6 + 5];
        float U[3][3];
#pragma unroll
        for (int r = 0; r < 3; ++r) {
            U[r][0] = N0[r * 3 + 0] * r00 + N0[r * 3 + 1] * r01 + N0[r * 3 + 2] * r02;
            U[r][1] = N0[r * 3 + 0] * r01 + N0[r * 3 + 1] * r11 + N0[r * 3 + 2] * r12;
            U[r][2] = N0[r * 3 + 0] * r02 + N0[r * 3 + 1] * r12 + N0[r * 3 + 2] * r22;
        }
#pragma unroll
        for (int r = 0; r < 3; ++r)
#pragma unroll
            for (int c = r; c < 3; ++c)
                C[a * 6 + S3(r, c)] =
                    U[r][0] * N0[c * 3 + 0] + U[r][1] * N0[c * 3 + 1] + U[r][2] * N0[c * 3 + 2];
    }

    // M blocks via x1-side congruence
    float ms[45];
#pragma unroll
    for (int ip = 0; ip < 3; ++ip) {
#pragma unroll
        for (int kp = 0; kp < 3; ++kp) {
            if (kp < ip) continue;
            float wc[6];
            wc[S3(0, 0)] = N1[ip * 3 + 0] * N1[kp * 3 + 0];
            wc[S3(1, 1)] = N1[ip * 3 + 1] * N1[kp * 3 + 1];
            wc[S3(2, 2)] = N1[ip * 3 + 2] * N1[kp * 3 + 2];
            wc[S3(0, 1)] = N1[ip * 3 + 0] * N1[kp * 3 + 1] + N1[ip * 3 + 1] * N1[kp * 3 + 0];
            wc[S3(0, 2)] = N1[ip * 3 + 0] * N1[kp * 3 + 2] + N1[ip * 3 + 2] * N1[kp * 3 + 0];
            wc[S3(1, 2)] = N1[ip * 3 + 1] * N1[kp * 3 + 2] + N1[ip * 3 + 2] * N1[kp * 3 + 1];
            float D[6];
#pragma unroll
            for (int q = 0; q < 6; ++q) {
                float s = 0.f;
#pragma unroll
                for (int p = 0; p < 6; ++p) s += wc[p] * C[p * 6 + q];
                D[q] = s;
            }
#pragma unroll
            for (int jp = 0; jp < 3; ++jp)
#pragma unroll
                for (int lp = 0; lp < 3; ++lp) {
                    int r = 3 * ip + jp, c = 3 * kp + lp;
                    if (c < r) continue;
                    int jj = (jp < lp) ? jp : lp;
                    int ll = (jp < lp) ? lp : jp;
                    ms[SU(r, c)] = D[S3(jj, ll)];
                }
        }
    }

    float tr = 0.f;
#pragma unroll
    for (int k = 0; k < 9; ++k) tr += ms[SU(k, k)];
    float eps = 1e-7f * tr;
#pragma unroll
    for (int k = 0; k < 9; ++k) ms[SU(k, k)] += eps;

    float L[45], invd[9];
    chol9(ms, 0.f, L, invd);

    float v[9];
#pragma unroll
    for (int i = 0; i < 9; ++i) v[i] = 1.f / 3.f;

    float z[9];
#pragma unroll
    for (int it = 0; it < 8; ++it) {   // 8 steps: proven sufficient
        cholsolve9(L, invd, v, z);
        float nn = 0.f;
#pragma unroll
        for (int i = 0; i < 9; ++i) nn += z[i] * z[i];
        float inv = rsqrtf(nn);
#pragma unroll
        for (int i = 0; i < 9; ++i) v[i] = z[i] * inv;
    }
    float rho = 0.f;
#pragma unroll
    for (int i = 0; i < 9; ++i) {
        float t = 0.f;
#pragma unroll
        for (int j = 0; j < 9; ++j) t += ASYM(ms, i, j) * v[j];
        rho += v[i] * t;
    }
    chol9(ms, 0.95f * rho, L, invd);
#pragma unroll
    for (int it = 0; it < 3; ++it) {
        cholsolve9(L, invd, v, z);
        float nn = 0.f;
#pragma unroll
        for (int i = 0; i < 9; ++i) nn += z[i] * z[i];
        float inv = rsqrtf(nn);
#pragma unroll
        for (int i = 0; i < 9; ++i) v[i] = z[i] * inv;
    }

    float E[3][3];
#pragma unroll
    for (int i = 0; i < 3; ++i)
#pragma unroll
        for (int j = 0; j < 3; ++j) E[i][j] = v[3 * i + j];

    float G[3][3];
#pragma unroll
    for (int i = 0; i < 3; ++i)
#pragma unroll
        for (int j = 0; j < 3; ++j) {
            float s = 0.f;
#pragma unroll
            for (int k = 0; k < 3; ++k) s += E[k][i] * E[k][j];
            G[i][j] = s;
        }
    float ev[3][3] = {{1.f,0.f,0.f},{0.f,1.f,0.f},{0.f,0.f,1.f}};

#define J3(P, Q, R) do {                                                      \
    float app = G[P][P], aqq = G[Q][Q], apq = G[P][Q];                        \
    if (fabsf(apq) > 1e-14f * (fabsf(app) + fabsf(aqq))) {                    \
        float tau = (aqq - app) / (2.f * apq);                                \
        float tt  = copysignf(1.f, tau) / (fabsf(tau) + sqrtf(1.f + tau * tau)); \
        float c   = 1.f / sqrtf(1.f + tt * tt);                               \
        float s   = tt * c;                                                   \
        float apr = G[P][R], aqr = G[Q][R];                                   \
        G[P][P] = app - tt * apq; G[Q][Q] = aqq + tt * apq;                   \
        G[P][Q] = 0.f; G[Q][P] = 0.f;                                         \
        G[P][R] = c * apr - s * aqr; G[R][P] = G[P][R];                       \
        G[Q][R] = s * apr + c * aqr; G[R][Q] = G[Q][R];                       \
        for (int kk = 0; kk < 3; ++kk) {                                      \
            float vp = ev[kk][P], vq = ev[kk][Q];                             \
            ev[kk][P] = c * vp - s * vq;                                      \
            ev[kk][Q] = s * vp + c * vq;                                      \
        }                                                                     \
    } } while (0)

#pragma unroll
    for (int sw = 0; sw < 8; ++sw) { J3(0, 1, 2); J3(0, 2, 1); J3(1, 2, 0); }
#undef J3

    float l0 = G[0][0], l1 = G[1][1], l2 = G[2][2];
    int i0 = 0, i1 = 1, i2 = 2;
    if (l1 > l0) { float tm = l0; l0 = l1; l1 = tm; int ti = i0; i0 = i1; i1 = ti; }
    if (l2 > l0) { float tm = l0; l0 = l2; l2 = tm; int ti = i0; i0 = i2; i2 = ti; }
    if (l2 > l1) { float tm = l1; l1 = l2; l2 = tm; int ti = i1; i1 = i2; i2 = ti; }

    float v1[3], v2[3], v3[3];
#pragma unroll
    for (int k = 0; k < 3; ++k) { v1[k] = ev[k][i0]; v2[k] = ev[k][i1]; v3[k] = ev[k][i2]; }

    float u1[3], u2[3], u3[3];
#pragma unroll
    for (int i = 0; i < 3; ++i)
        u1[i] = E[i][0] * v1[0] + E[i][1] * v1[1] + E[i][2] * v1[2];
    {
        float nn = rsqrtf(u1[0]*u1[0] + u1[1]*u1[1] + u1[2]*u1[2]);
        u1[0] *= nn; u1[1] *= nn; u1[2] *= nn;
    }
#pragma unroll
    for (int i = 0; i < 3; ++i)
        u2[i] = E[i][0] * v2[0] + E[i][1] * v2[1] + E[i][2] * v2[2];
    {
        float d = u1[0]*u2[0] + u1[1]*u2[1] + u1[2]*u2[2];
        u2[0] -= d * u1[0]; u2[1] -= d * u1[1]; u2[2] -= d * u1[2];
        float nn = rsqrtf(u2[0]*u2[0] + u2[1]*u2[1] + u2[2]*u2[2]);
        u2[0] *= nn; u2[1] *= nn; u2[2] *= nn;
    }
    u3[0] = u1[1] * u2[2] - u1[2] * u2[1];
    u3[1] = u1[2] * u2[0] - u1[0] * u2[2];
    u3[2] = u1[0] * u2[1] - u1[1] * u2[0];

    float Ev3[3];
#pragma unroll
    for (int i = 0; i < 3; ++i)
        Ev3[i] = E[i][0] * v3[0] + E[i][1] * v3[1] + E[i][2] * v3[2];
    float s3p = u3[0]*Ev3[0] + u3[1]*Ev3[1] + u3[2]*Ev3[2];
    if (s3p < 0.f) { v3[0] = -v3[0]; v3[1] = -v3[1]; v3[2] = -v3[2]; }

    float R1[9], R2[9];
#pragma unroll
    for (int i = 0; i < 3; ++i)
#pragma unroll
        for (int j = 0; j < 3; ++j) {
            float c3 = u3[i] * v3[j];
            R1[3 * i + j] =  u2[i] * v1[j] - u1[i] * v2[j] + c3;
            R2[3 * i + j] = -u2[i] * v1[j] + u1[i] * v2[j] + c3;
        }
    float d1 = R1[0]*(R1[4]*R1[8]-R1[5]*R1[7]) - R1[1]*(R1[3]*R1[8]-R1[5]*R1[6]) + R1[2]*(R1[3]*R1[7]-R1[4]*R1[6]);
    float d2 = R2[0]*(R2[4]*R2[8]-R2[5]*R2[7]) - R2[1]*(R2[3]*R2[8]-R2[5]*R2[6]) + R2[2]*(R2[3]*R2[7]-R2[4]*R2[6]);
    float sg1 = (d1 < 0.f) ? -1.f : 1.f;
    float sg2 = (d2 < 0.f) ? -1.f : 1.f;
#pragma unroll
    for (int m = 0; m < 9; ++m) { out48[m] = R1[m] * sg1; out48[9 + m] = R2[m] * sg2; }
    out48[18] = u3[0]; out48[19] = u3[1]; out48[20] = u3[2];
    // prefused score matrices: A1 = R1s*N0, A2 = R2s*N0, and N1
#pragma unroll
    for (int r = 0; r < 3; ++r)
#pragma unroll
        for (int c = 0; c < 3; ++c) {
            float s1 = 0.f, s2 = 0.f;
#pragma unroll
            for (int k = 0; k < 3; ++k) {
                s1 += out48[r * 3 + k] * N0[k * 3 + c];
                s2 += out48[9 + r * 3 + k] * N0[k * 3 + c];
            }
            out48[21 + r * 3 + c] = s1;
            out48[30 + r * 3 + c] = s2;
        }
#pragma unroll
    for (int m = 0; m < 9; ++m) out48[39 + m] = N1[m];
}

// ---------------------------------------------------------------------------
// Single fused kernel: one block per batch.
//   pass 1: load+precondition -> smem cache + 36-moment accumulation
//   thread 0: congruence + eigen/SVD solve -> shared candidates
//   pass 2: cheirality scoring from smem, reduce, write T01/T10
// ---------------------------------------------------------------------------
__global__ void __launch_bounds__(256, 2) k_fused(
    const float* __restrict__ kpts0, const float* __restrict__ kpts1,
    const float* __restrict__ conf,  const float* __restrict__ tscale,
    const float* __restrict__ K, float* __restrict__ out, int N)
{
    extern __shared__ float sdyn[];          // [4096 float4 pts][4096 w] = 80KB
    float4* spt = (float4*)sdyn;
    float*  sw  = sdyn + 4096 * 4;

    __shared__ float red[8][36];
    __shared__ float Tsm[36];
    __shared__ float cand[48];

    int b = blockIdx.x;
    int tid = threadIdx.x;

    float acc[36];
#pragma unroll
    for (int m = 0; m < 36; ++m) acc[m] = 0.f;

    const float4* p0v = (const float4*)(kpts0 + (size_t)b * N * 2);
    const float4* p1v = (const float4*)(kpts1 + (size_t)b * N * 2);
    const float4* pwv = (const float4*)(conf  + (size_t)b * N);
    const float2* p0  = (const float2*)(kpts0 + (size_t)b * N * 2);
    const float2* p1  = (const float2*)(kpts1 + (size_t)b * N * 2);
    const float*  pw  = conf + (size_t)b * N;

    auto accum_pt = [&](float x0p, float y0p, float x1p, float y1p, float w) {
        float P[6], Q[6];
        P[0] = x1p * x1p; P[1] = x1p * y1p; P[2] = x1p;
        P[3] = y1p * y1p; P[4] = y1p;      P[5] = 1.f;
        Q[0] = x0p * x0p; Q[1] = x0p * y0p; Q[2] = x0p;
        Q[3] = y0p * y0p; Q[4] = y0p;      Q[5] = 1.f;
#pragma unroll
        for (int a = 0; a < 6; ++a) {
            float t = w * P[a];
#pragma unroll
            for (int q = 0; q < 6; ++q)
                acc[a * 6 + q] = fmaf(t, Q[q], acc[a * 6 + q]);
        }
    };

    const bool fast = (N == 4096);
    if (fast) {
        int base = tid * 16;
#pragma unroll
        for (int h = 0; h < 2; ++h) {
            int nb = base + h * 8;
            float4 a0[4], a1[4], wv[2];
            int q4 = nb >> 1;
#pragma unroll
            for (int k = 0; k < 4; ++k) { a0[k] = p0v[q4 + k]; a1[k] = p1v[q4 + k]; }
            wv[0] = pwv[nb >> 2];
            wv[1] = pwv[(nb >> 2) + 1];
            const float* wf = (const float*)wv;
#pragma unroll
            for (int j = 0; j < 8; ++j) {
                float ux0 = (j & 1) ? a0[j >> 1].z : a0[j >> 1].x;
                float uy0 = (j & 1) ? a0[j >> 1].w : a0[j >> 1].y;
                float ux1 = (j & 1) ? a1[j >> 1].z : a1[j >> 1].x;
                float uy1 = (j & 1) ? a1[j >> 1].w : a1[j >> 1].y;
                float x0p = fmaf(ux0, PSX, -1.f);
                float y0p = fmaf(uy0, PSY, -1.f);
                float x1p = fmaf(ux1, PSX, -1.f);
                float y1p = fmaf(uy1, PSY, -1.f);
                float w = wf[j];
                int jj = h * 8 + j;               // per-thread point index 0..15
                spt[jj * 256 + tid] = make_float4(x0p, y0p, x1p, y1p);
                sw[jj * 256 + tid] = w;
                accum_pt(x0p, y0p, x1p, y1p, w);
            }
        }
    } else {
        for (int n = tid; n < N; n += 256) {
            float2 u0 = p0[n];
            float2 u1 = p1[n];
            float w = pw[n];
            accum_pt(fmaf(u0.x, PSX, -1.f), fmaf(u0.y, PSY, -1.f),
                     fmaf(u1.x, PSX, -1.f), fmaf(u1.y, PSY, -1.f), w);
        }
    }

    // block reduction of 36 moments
    int lane = tid & 31, wid = tid >> 5;
#pragma unroll
    for (int m = 0; m < 36; ++m) {
#pragma unroll
        for (int o = 16; o > 0; o >>= 1)
            acc[m] += __shfl_xor_sync(0xffffffffu, acc[m], o);
    }
    if (lane == 0) {
#pragma unroll
        for (int m = 0; m < 36; ++m) red[wid][m] = acc[m];
    }
    __syncthreads();
    if (tid < 36) {
        float sum = 0.f;
#pragma unroll
        for (int wd = 0; wd < 8; ++wd) sum += red[wd][tid];
        Tsm[tid] = sum;
    }
    __syncthreads();

    if (tid == 0)
        solve_from_T(Tsm, K, b, cand);
    __syncthreads();

    // load candidates (broadcast smem reads)
    float A1[9], A2[9], N1l[9], tv[3];
#pragma unroll
    for (int m = 0; m < 9; ++m) {
        A1[m]  = cand[21 + m];
        A2[m]  = cand[30 + m];
        N1l[m] = cand[39 + m];
    }
    tv[0] = cand[18]; tv[1] = cand[19]; tv[2] = cand[20];

    float sc[4] = {0.f, 0.f, 0.f, 0.f};

    auto score_pt = [&](float x0p, float y0p, float x1p, float y1p, float w) {
        float b0 = fmaf(N1l[0], x1p, fmaf(N1l[1], y1p, N1l[2]));
        float b1 = fmaf(N1l[3], x1p, fmaf(N1l[4], y1p, N1l[5]));
        float b2 = fmaf(N1l[6], x1p, fmaf(N1l[7], y1p, N1l[8]));
        float bb = b0 * b0 + b1 * b1 + b2 * b2;
        float bt = b0 * tv[0] + b1 * tv[1] + b2 * tv[2];
        {
            float a0 = fmaf(A1[0], x0p, fmaf(A1[1], y0p, A1[2]));
            float a1 = fmaf(A1[3], x0p, fmaf(A1[4], y0p, A1[5]));
            float a2 = fmaf(A1[6], x0p, fmaf(A1[7], y0p, A1[8]));
            float aa = a0 * a0 + a1 * a1 + a2 * a2;
            float ab = a0 * b0 + a1 * b1 + a2 * b2;
            float at = a0 * tv[0] + a1 * tv[1] + a2 * tv[2];
            float n0v = ab * bt - at * bb;
            float n1v = aa * bt - ab * at;
            if (n0v > 0.f && n1v > 0.f) sc[0] += w;
            if (n0v < 0.f && n1v < 0.f) sc[1] += w;
        }
        {
            float a0 = fmaf(A2[0], x0p, fmaf(A2[1], y0p, A2[2]));
            float a1 = fmaf(A2[3], x0p, fmaf(A2[4], y0p, A2[5]));
            float a2 = fmaf(A2[6], x0p, fmaf(A2[7], y0p, A2[8]));
            float aa = a0 * a0 + a1 * a1 + a2 * a2;
            float ab = a0 * b0 + a1 * b1 + a2 * b2;
            float at = a0 * tv[0] + a1 * tv[1] + a2 * tv[2];
            float n0v = ab * bt - at * bb;
            float n1v = aa * bt - ab * at;
            if (n0v > 0.f && n1v > 0.f) sc[2] += w;
            if (n0v < 0.f && n1v < 0.f) sc[3] += w;
        }
    };

    if (fast) {
#pragma unroll
        for (int jj = 0; jj < 16; ++jj) {
            float4 p = spt[jj * 256 + tid];
            float w = sw[jj * 256 + tid];
            score_pt(p.x, p.y, p.z, p.w, w);
        }
    } else {
        for (int n = tid; n < N; n += 256) {
            float2 u0 = p0[n];
            float2 u1 = p1[n];
            float w = pw[n];
            score_pt(fmaf(u0.x, PSX, -1.f), fmaf(u0.y, PSY, -1.f),
                     fmaf(u1.x, PSX, -1.f), fmaf(u1.y, PSY, -1.f), w);
        }
    }

    // score reduction (reuse red; everyone is past the post-solve barrier)
#pragma unroll
    for (int m = 0; m < 4; ++m) {
#pragma unroll
        for (int o = 16; o > 0; o >>= 1)
            sc[m] += __shfl_xor_sync(0xffffffffu, sc[m], o);
    }
    if (lane == 0) {
#pragma unroll
        for (int m = 0; m < 4; ++m) red[wid][m] = sc[m];
    }
    __syncthreads();

    if (tid == 0) {
        float stot[4];
#pragma unroll
        for (int m = 0; m < 4; ++m) {
            float sum = 0.f;
#pragma unroll
            for (int wd = 0; wd < 8; ++wd) sum += red[wd][m];
            stot[m] = sum;
        }
        int best = 0;
        for (int c = 1; c < 4; ++c) if (stot[c] > stot[best]) best = c;

        const float* Rs = (best < 2) ? cand : cand + 9;
        float R[9];
#pragma unroll
        for (int m = 0; m < 9; ++m) R[m] = Rs[m];
        float sg = (best & 1) ? -1.f : 1.f;
        float ts = tscale[(size_t)b * 2];
        float t0 = sg * tv[0] * ts, t1 = sg * tv[1] * ts, t2 = sg * tv[2] * ts;

        float* o01 = out + (size_t)b * 32;
        float* o10 = o01 + 16;
        o01[0]  = R[0]; o01[1]  = R[1]; o01[2]  = R[2]; o01[3]  = t0;
        o01[4]  = R[3]; o01[5]  = R[4]; o01[6]  = R[5]; o01[7]  = t1;
        o01[8]  = R[6]; o01[9]  = R[7]; o01[10] = R[8]; o01[11] = t2;
        o01[12] = 0.f;  o01[13] = 0.f;  o01[14] = 0.f;  o01[15] = 1.f;
        float ti0 = -(R[0] * t0 + R[3] * t1 + R[6] * t2);
        float ti1 = -(R[1] * t0 + R[4] * t1 + R[7] * t2);
        float ti2 = -(R[2] * t0 + R[5] * t1 + R[8] * t2);
        o10[0]  = R[0]; o10[1]  = R[3]; o10[2]  = R[6]; o10[3]  = ti0;
        o10[4]  = R[1]; o10[5]  = R[4]; o10[6]  = R[7]; o10[7]  = ti1;
        o10[8]  = R[2]; o10[9]  = R[5]; o10[10] = R[8]; o10[11] = ti2;
        o10[12] = 0.f;  o10[13] = 0.f;  o10[14] = 0.f;  o10[15] = 1.f;
    }
}

// ---------------------------------------------------------------------------
extern "C" void kernel_launch(void* const* d_in, const int* in_sizes, int n_in,
                              void* d_out, int out_size)
{
    const float* kpts0 = (const float*)d_in[0];
    const float* kpts1 = (const float*)d_in[1];
    const float* conf  = (const float*)d_in[2];
    const float* tsc   = (const float*)d_in[3];
    const float* K     = (const float*)d_in[4];

    int B = in_sizes[4] / 18;        // K: (B, 2, 3, 3)
    int N = in_sizes[2] / B;         // conf: (B, N, 1)

    static bool attr_set = false;
    if (!attr_set) {
        cudaFuncSetAttribute(k_fused, cudaFuncAttributeMaxDynamicSharedMemorySize,
                             84 * 1024);
        attr_set = true;
    }
    size_t shmem = (N == 4096) ? (size_t)(4096 * 5 * sizeof(float)) : 0;
    k_fused<<<B, 256, shmem>>>(kpts0, kpts1, conf, tsc, K, (float*)d_out, N);
}